// round 5
// baseline (speedup 1.0000x reference)
#include <cuda_runtime.h>
#include <cuda_fp16.h>
#include <math.h>

#define B_    16
#define NPTS  2048
#define PCTR  256
#define KNB   32
#define HW    1920
#define INFEA 64
#define MTOT  131072
#define EPSBN 1e-5f
#define DIST_ 0.5f
#define OUTSTRIDE 5242880   // 640*8192

// ---------------- scratch ----------------
__device__ __half g_X0h[80 * MTOT];   // channels 67..79 stay zero (zero-init, never written)
__device__ __half g_Y1h[64 * MTOT];
__device__ __half g_Y2h[128 * MTOT];
__device__ __half g_Y3h[128 * MTOT];
__device__ __half g_Y4h[256 * MTOT];
__device__ int    g_idx[MTOT];
__device__ int    g_ridx[MTOT];
__device__ float  g_vmask[B_ * PCTR];
__device__ unsigned g_Wp1[40 * 64];    // half2 packed [CINP/2][M]
__device__ unsigned g_Wp2[32 * 128];
__device__ unsigned g_Wp3[64 * 128];
__device__ unsigned g_Wp4[64 * 256];
__device__ float  g_sum[4][256];
__device__ float  g_sq[4][256];
__device__ float  g_sc[4][256];
__device__ float  g_sh[4][256];
__device__ unsigned g_cnt[4];

__device__ __forceinline__ void cp16(void* dst_smem, const void* src) {
    unsigned d = (unsigned)__cvta_generic_to_shared(dst_smem);
    asm volatile("cp.async.cg.shared.global [%0], [%1], 16;" :: "r"(d), "l"(src));
}

// ---------------- depth-ball query (+ zero stats & counters) ----------------
__global__ void k_idx(const float* __restrict__ pc,
                      const float* __restrict__ npc,
                      const int*   __restrict__ qv1)
{
    __shared__ float zs[NPTS];
    __shared__ int   stage[8][32];
    const int b   = blockIdx.x;
    const int tid = threadIdx.x;

    if (b == 0) {
        float* ps = &g_sum[0][0];
        float* pq = &g_sq[0][0];
        for (int i = tid; i < 4 * 256; i += 256) { ps[i] = 0.f; pq[i] = 0.f; }
        if (tid < 4) g_cnt[tid] = 0u;
    }
    for (int i = tid; i < NPTS; i += 256) zs[i] = pc[(b * 3 + 2) * NPTS + i];
    __syncthreads();

    const int w = tid >> 5, lane = tid & 31;
    for (int jj = 0; jj < 32; jj++) {
        const int j = w * 32 + jj;
        const float cz = npc[(b * 3 + 2) * PCTR + j];
        int cnt = 0;
        for (int c = 0; c < NPTS / 32; c++) {
            const int n = c * 32 + lane;
            const bool hit = fabsf(zs[n] - cz) < DIST_;
            const unsigned bal = __ballot_sync(0xffffffffu, hit);
            if (hit) {
                const int pos = cnt + __popc(bal & ((1u << lane) - 1u));
                if (pos < 32) stage[w][pos] = n;
            }
            cnt += __popc(bal);
            if (cnt >= 32) break;
        }
        __syncwarp();
        const int cc = min(cnt, 32);
        const int first = (cnt > 0) ? stage[w][0] : 0;
        const int v = (lane < cc) ? stage[w][lane] : first;
        const int gbase = (b * PCTR + j) * KNB;
        g_idx[gbase + lane]  = v;
        g_ridx[gbase + lane] = qv1[b * NPTS + v];
        if (lane == 0) g_vmask[b * PCTR + j] = (cnt > 0) ? 1.f : 0.f;
        __syncwarp();
    }
}

// ---------------- weight packing ----------------
__device__ __forceinline__ void packW(const float* w, unsigned* dst,
                                      int M, int CIN, int CINP, int tid, int nthr)
{
    const int tot = (CINP / 2) * M;
    for (int i = tid; i < tot; i += nthr) {
        const int p = i / M, m = i - p * M;
        const int k0 = 2 * p, k1 = 2 * p + 1;
        const float a = (k0 < CIN) ? w[m * CIN + k0] : 0.f;
        const float b = (k1 < CIN) ? w[m * CIN + k1] : 0.f;
        __half2 h = __floats2half2_rn(a, b);
        dst[i] = *(unsigned*)&h;
    }
}

__global__ void k_prep(const float* __restrict__ w1, const float* __restrict__ w2,
                       const float* __restrict__ w3, const float* __restrict__ w4)
{
    const int tid = blockIdx.x * blockDim.x + threadIdx.x;
    const int nthr = gridDim.x * blockDim.x;
    packW(w1, g_Wp1, 64, 67, 80, tid, nthr);
    packW(w2, g_Wp2, 128, 64, 64, tid, nthr);
    packW(w3, g_Wp3, 128, 128, 128, tid, nthr);
    packW(w4, g_Wp4, 256, 128, 128, tid, nthr);
}

// ---------------- gather X0 (half) + rgb -> out ----------------
__global__ void k_gather(const float* __restrict__ pc,
                         const float* __restrict__ feat,
                         const float* __restrict__ img1,
                         const float* __restrict__ img2,
                         const float* __restrict__ npc,
                         float* __restrict__ out)
{
    __shared__ int   s_idx[32];
    __shared__ int   s_rid[32];
    __shared__ float s_np[3];
    __shared__ float s_vm;
    const int g = blockIdx.x;
    const int b = g >> 8;
    const int j = g & 255;
    const int t = threadIdx.x;
    const int mbase = g * KNB;

    if (t < 32) { s_idx[t] = g_idx[mbase + t]; s_rid[t] = g_ridx[mbase + t]; }
    if (t >= 32 && t < 35) s_np[t - 32] = npc[(b * 3 + (t - 32)) * PCTR + j];
    if (t == 40) s_vm = g_vmask[g];
    __syncthreads();

    const float vm = s_vm;
    const long ob = (long)b * OUTSTRIDE + (long)j * 32;

    if (t < 96) {
        const int c = t >> 5, k = t & 31;
        g_X0h[c * MTOT + mbase + k] =
            __float2half(pc[(b * 3 + c) * NPTS + s_idx[k]] - s_np[c]);
    }
    for (int e = t; e < INFEA * 32; e += 256) {
        const int c = e >> 5, k = e & 31;
        g_X0h[(3 + c) * MTOT + mbase + k] =
            __float2half(feat[(b * INFEA + c) * NPTS + s_idx[k]]);
    }
    for (int e = t; e < 64 * 32; e += 256) {
        const int c = e >> 5, k = e & 31;
        out[ob + (long)(64 + c) * 8192 + k] = img1[(b * 64 + c) * HW + s_rid[k]] * vm;
    }
    for (int e = t; e < 128 * 32; e += 256) {
        const int c = e >> 5, k = e & 31;
        out[ob + (long)(256 + c) * 8192 + k] = img2[(b * 128 + c) * HW + s_rid[k]] * vm;
    }
}

// ---------------- fp16 tensor-core GEMM, cp.async + double buffer ----------------
// Y(half) = W @ f(X); fused: channel stats, optional fp32 out write of f(X),
// last-block BN finalize (scale/shift for this layer).
template <int BM, int CIN, bool NORM_IN, int OUTC, int THREADS>
__global__ void __launch_bounds__(THREADS)
k_gemm_h(const unsigned* __restrict__ Wp, const __half* __restrict__ X,
         __half* __restrict__ Y,
         const float* __restrict__ isc, const float* __restrict__ ish,
         float* __restrict__ osum, float* __restrict__ osq,
         float* __restrict__ out,
         const float* __restrict__ gam, const float* __restrict__ bet,
         float* __restrict__ sc, float* __restrict__ sh,
         unsigned* __restrict__ cnt)
{
    constexpr int BN = 128, BK = 16, KP = 8;
    constexpr int NITER = CIN / BK;
    constexpr int WARPS_M = THREADS / 128;      // 4 warps along N
    constexpr int WTM = BM / WARPS_M;
    constexpr int MI = WTM / 16;
    constexpr int AIT = KP * (BM / 4);          // uint4 per A stage
    constexpr int BIT = KP * (BN / 4);          // uint4 per B stage (=256)
    constexpr int BITER = (BIT + THREADS - 1) / THREADS;

    __shared__ __half2 As2[2][KP][BM + 8];
    __shared__ __half2 Bs2[2][KP][BN + 8];
    __shared__ float redS[BM], redQ[BM];
    __shared__ int s_last;

    const int tid  = threadIdx.x;
    const int lane = tid & 31;
    const int warp = tid >> 5;
    const int wm0  = (warp >> 2) * WTM;
    const int wn0  = (warp & 3) * 32;
    const int bn0  = blockIdx.x * BN;
    const int grp  = lane >> 2;
    const int tig  = lane & 3;

    uint4 bReg[BITER];

    auto cpA = [&](int k0, int buf) {
        for (int f = tid; f < AIT; f += THREADS) {
            const int kk2 = f / (BM / 4), m4 = f % (BM / 4);
            cp16(&As2[buf][kk2][m4 * 4], &Wp[(k0 / 2 + kk2) * BM + m4 * 4]);
        }
        asm volatile("cp.async.commit_group;");
    };
    auto loadB = [&](int k0) {
#pragma unroll
        for (int u = 0; u < BITER; u++) {
            const int e = tid + u * THREADS;
            if (e >= BIT) break;
            const int kk2 = e >> 5;
            const int n = bn0 + (e & 31) * 4;
            const int k = k0 + 2 * kk2;
            const uint2 r0 = *(const uint2*)&X[(size_t)k * MTOT + n];
            const uint2 r1 = *(const uint2*)&X[(size_t)(k + 1) * MTOT + n];
            const __half* h0 = (const __half*)&r0;
            const __half* h1 = (const __half*)&r1;
            float v0[4], v1[4];
#pragma unroll
            for (int j = 0; j < 4; j++) { v0[j] = __half2float(h0[j]); v1[j] = __half2float(h1[j]); }
            if (NORM_IN) {
                const float s0 = isc[k], t0 = ish[k];
                const float s1 = isc[k + 1], t1 = ish[k + 1];
#pragma unroll
                for (int j = 0; j < 4; j++) {
                    v0[j] = fmaxf(v0[j] * s0 + t0, 0.f);
                    v1[j] = fmaxf(v1[j] * s1 + t1, 0.f);
                }
            }
            if (OUTC >= 0) {
                const float vm = g_vmask[n >> 5];
                const int bb = n >> 13, rem = n & 8191;
                float* op = &out[(long)bb * OUTSTRIDE + (long)(OUTC + k) * 8192 + rem];
                *(float4*)op = make_float4(v0[0] * vm, v0[1] * vm, v0[2] * vm, v0[3] * vm);
                op += 8192;
                *(float4*)op = make_float4(v1[0] * vm, v1[1] * vm, v1[2] * vm, v1[3] * vm);
            }
            __half2 h[4];
#pragma unroll
            for (int j = 0; j < 4; j++) h[j] = __floats2half2_rn(v0[j], v1[j]);
            bReg[u] = *(uint4*)h;
        }
    };
    auto storeB = [&](int buf) {
#pragma unroll
        for (int u = 0; u < BITER; u++) {
            const int e = tid + u * THREADS;
            if (e >= BIT) break;
            const int kk2 = e >> 5;
            const int n4 = e & 31;
            *(uint4*)&Bs2[buf][kk2][n4 * 4] = bReg[u];
        }
    };

    float acc[MI][4][4];
#pragma unroll
    for (int mi = 0; mi < MI; mi++)
#pragma unroll
        for (int ni = 0; ni < 4; ni++)
#pragma unroll
            for (int r = 0; r < 4; r++) acc[mi][ni][r] = 0.f;

    // prologue
    cpA(0, 0);
    loadB(0);
    storeB(0);
    asm volatile("cp.async.wait_group 0;");
    __syncthreads();

    for (int it = 0; it < NITER; it++) {
        const int buf = it & 1, nxt = buf ^ 1;
        if (it + 1 < NITER) {
            cpA((it + 1) * BK, nxt);
            loadB((it + 1) * BK);
            storeB(nxt);
        }
        // compute on buf
        unsigned a[MI][4], b[4][2];
#pragma unroll
        for (int mi = 0; mi < MI; mi++) {
            const int row = wm0 + mi * 16 + grp;
            a[mi][0] = *(const unsigned*)&As2[buf][tig][row];
            a[mi][1] = *(const unsigned*)&As2[buf][tig][row + 8];
            a[mi][2] = *(const unsigned*)&As2[buf][tig + 4][row];
            a[mi][3] = *(const unsigned*)&As2[buf][tig + 4][row + 8];
        }
#pragma unroll
        for (int ni = 0; ni < 4; ni++) {
            const int col = wn0 + ni * 8 + grp;
            b[ni][0] = *(const unsigned*)&Bs2[buf][tig][col];
            b[ni][1] = *(const unsigned*)&Bs2[buf][tig + 4][col];
        }
#pragma unroll
        for (int mi = 0; mi < MI; mi++)
#pragma unroll
            for (int ni = 0; ni < 4; ni++) {
                asm volatile(
                    "mma.sync.aligned.m16n8k16.row.col.f32.f16.f16.f32 "
                    "{%0,%1,%2,%3}, {%4,%5,%6,%7}, {%8,%9}, {%0,%1,%2,%3};"
                    : "+f"(acc[mi][ni][0]), "+f"(acc[mi][ni][1]),
                      "+f"(acc[mi][ni][2]), "+f"(acc[mi][ni][3])
                    : "r"(a[mi][0]), "r"(a[mi][1]), "r"(a[mi][2]), "r"(a[mi][3]),
                      "r"(b[ni][0]), "r"(b[ni][1]));
            }
        asm volatile("cp.async.wait_group 0;");
        __syncthreads();
    }

    // ---- epilogue: Y(half) + stats ----
    for (int e = tid; e < BM; e += THREADS) { redS[e] = 0.f; redQ[e] = 0.f; }
    __syncthreads();

#pragma unroll
    for (int mi = 0; mi < MI; mi++) {
        const int r1 = wm0 + mi * 16 + grp;
        const int r2 = r1 + 8;
        float s1 = 0.f, q1 = 0.f, s2 = 0.f, q2 = 0.f;
#pragma unroll
        for (int ni = 0; ni < 4; ni++) {
            const int col = bn0 + wn0 + ni * 8 + tig * 2;
            const float c0 = acc[mi][ni][0], c1 = acc[mi][ni][1];
            const float c2 = acc[mi][ni][2], c3 = acc[mi][ni][3];
            *(__half2*)&Y[(size_t)r1 * MTOT + col] = __floats2half2_rn(c0, c1);
            *(__half2*)&Y[(size_t)r2 * MTOT + col] = __floats2half2_rn(c2, c3);
            s1 += c0 + c1;  q1 += c0 * c0 + c1 * c1;
            s2 += c2 + c3;  q2 += c2 * c2 + c3 * c3;
        }
        atomicAdd(&redS[r1], s1);
        atomicAdd(&redQ[r1], q1);
        atomicAdd(&redS[r2], s2);
        atomicAdd(&redQ[r2], q2);
    }
    __syncthreads();
    for (int e = tid; e < BM; e += THREADS) {
        atomicAdd(&osum[e], redS[e]);
        atomicAdd(&osq[e], redQ[e]);
    }

    // ---- last block finalizes BN scale/shift ----
    __threadfence();
    __syncthreads();
    if (tid == 0) {
        const unsigned done = atomicAdd(cnt, 1u);
        s_last = (done == gridDim.x - 1) ? 1 : 0;
    }
    __syncthreads();
    if (s_last) {
        __threadfence();
        for (int c = tid; c < BM; c += THREADS) {
            const float m = osum[c] * (1.f / (float)MTOT);
            const float v = osq[c] * (1.f / (float)MTOT) - m * m;
            const float s = gam[c] * rsqrtf(v + EPSBN);
            sc[c] = s;
            sh[c] = bet[c] - m * s;
        }
    }
}

// ---------------- final norm_out for Y4 (half in, fp32 out) ----------------
__global__ void k_norm_out_h(const __half* __restrict__ Y, int layer, int C, int cbase,
                             float* __restrict__ out)
{
    const int T = C * (MTOT / 8);
    for (int e = blockIdx.x * blockDim.x + threadIdx.x; e < T;
         e += gridDim.x * blockDim.x) {
        const int c  = e / (MTOT / 8);
        const int m  = (e - c * (MTOT / 8)) * 8;
        const uint4 r = *(const uint4*)&Y[(size_t)c * MTOT + m];
        const __half* h = (const __half*)&r;
        const float s = g_sc[layer][c], t = g_sh[layer][c];
        const float vm = g_vmask[m >> 5];
        const int bb = m >> 13, rem = m & 8191;
        float* op = &out[(long)bb * OUTSTRIDE + (long)(cbase + c) * 8192 + rem];
        float4 o0, o1;
        o0.x = fmaxf(__half2float(h[0]) * s + t, 0.f) * vm;
        o0.y = fmaxf(__half2float(h[1]) * s + t, 0.f) * vm;
        o0.z = fmaxf(__half2float(h[2]) * s + t, 0.f) * vm;
        o0.w = fmaxf(__half2float(h[3]) * s + t, 0.f) * vm;
        o1.x = fmaxf(__half2float(h[4]) * s + t, 0.f) * vm;
        o1.y = fmaxf(__half2float(h[5]) * s + t, 0.f) * vm;
        o1.z = fmaxf(__half2float(h[6]) * s + t, 0.f) * vm;
        o1.w = fmaxf(__half2float(h[7]) * s + t, 0.f) * vm;
        *(float4*)op       = o0;
        *(float4*)(op + 4) = o1;
    }
}

// ---------------- launch ----------------
extern "C" void kernel_launch(void* const* d_in, const int* in_sizes, int n_in,
                              void* d_out, int out_size)
{
    const float* pc   = (const float*)d_in[0];
    const float* feat = (const float*)d_in[1];
    const float* img1 = (const float*)d_in[2];
    const float* img2 = (const float*)d_in[3];
    const int*   qv1  = (const int*)d_in[5];
    const float* npc  = (const float*)d_in[6];
    const float* w1 = (const float*)d_in[7];
    const float* g1 = (const float*)d_in[8];
    const float* b1 = (const float*)d_in[9];
    const float* w2 = (const float*)d_in[10];
    const float* g2 = (const float*)d_in[11];
    const float* b2 = (const float*)d_in[12];
    const float* w3 = (const float*)d_in[13];
    const float* g3 = (const float*)d_in[14];
    const float* b3 = (const float*)d_in[15];
    const float* w4 = (const float*)d_in[16];
    const float* g4 = (const float*)d_in[17];
    const float* b4 = (const float*)d_in[18];
    float* out = (float*)d_out;

    __half *pX0, *pY1, *pY2, *pY3, *pY4;
    unsigned *pW1, *pW2, *pW3, *pW4, *pCnt;
    float *pSum, *pSq, *pSc, *pSh;
    cudaGetSymbolAddress((void**)&pX0, g_X0h);
    cudaGetSymbolAddress((void**)&pY1, g_Y1h);
    cudaGetSymbolAddress((void**)&pY2, g_Y2h);
    cudaGetSymbolAddress((void**)&pY3, g_Y3h);
    cudaGetSymbolAddress((void**)&pY4, g_Y4h);
    cudaGetSymbolAddress((void**)&pW1, g_Wp1);
    cudaGetSymbolAddress((void**)&pW2, g_Wp2);
    cudaGetSymbolAddress((void**)&pW3, g_Wp3);
    cudaGetSymbolAddress((void**)&pW4, g_Wp4);
    cudaGetSymbolAddress((void**)&pSum, g_sum);
    cudaGetSymbolAddress((void**)&pSq,  g_sq);
    cudaGetSymbolAddress((void**)&pSc,  g_sc);
    cudaGetSymbolAddress((void**)&pSh,  g_sh);
    cudaGetSymbolAddress((void**)&pCnt, g_cnt);

    k_idx<<<B_, 256>>>(pc, npc, qv1);
    k_prep<<<32, 256>>>(w1, w2, w3, w4);
    k_gather<<<B_ * PCTR, 256>>>(pc, feat, img1, img2, npc, out);

    const int GX = MTOT / 128;

    // L1: 64 <- 80(pad of 67)
    k_gemm_h<64, 80, false, -1, 256><<<GX, 256>>>(pW1, pX0, pY1, nullptr, nullptr,
                                                  pSum + 0, pSq + 0, out,
                                                  g1, b1, pSc + 0, pSh + 0, pCnt + 0);
    // L2: 128 <- 64, norm-in(L1), writes bn(Y1) to out ch [0,64)
    k_gemm_h<128, 64, true, 0, 256><<<GX, 256>>>(pW2, pY1, pY2, pSc + 0, pSh + 0,
                                                 pSum + 256, pSq + 256, out,
                                                 g2, b2, pSc + 256, pSh + 256, pCnt + 1);
    // L3: 128 <- 128, norm-in(L2), writes bn(Y2) to out ch [128,256)
    k_gemm_h<128, 128, true, 128, 256><<<GX, 256>>>(pW3, pY2, pY3, pSc + 256, pSh + 256,
                                                    pSum + 512, pSq + 512, out,
                                                    g3, b3, pSc + 512, pSh + 512, pCnt + 2);
    // L4: 256 <- 128, norm-in(L3)
    k_gemm_h<256, 128, true, -1, 512><<<GX, 512>>>(pW4, pY3, pY4, pSc + 512, pSh + 512,
                                                   pSum + 768, pSq + 768, out,
                                                   g4, b4, pSc + 768, pSh + 768, pCnt + 3);

    // bn(Y4) -> out ch [384,640)
    k_norm_out_h<<<2048, 256>>>(pY4, 3, 256, 384, out);
}

// round 6
// speedup vs baseline: 1.0193x; 1.0193x over previous
#include <cuda_runtime.h>
#include <cuda_fp16.h>
#include <math.h>

#define B_    16
#define NPTS  2048
#define PCTR  256
#define KNB   32
#define HW    1920
#define INFEA 64
#define MTOT  131072
#define EPSBN 1e-5f
#define DIST_ 0.5f
#define OUTSTRIDE 5242880   // 640*8192

// ---------------- scratch ----------------
__device__ __half g_X0h[80 * MTOT];   // channels 67..79 stay zero
__device__ __half g_Y1h[64 * MTOT];
__device__ __half g_Y2h[128 * MTOT];
__device__ __half g_Y3h[128 * MTOT];
__device__ __half g_Y4h[256 * MTOT];
__device__ int    g_idx[MTOT];
__device__ int    g_ridx[MTOT];
__device__ float  g_vmask[B_ * PCTR];
__device__ unsigned g_Wp1[40 * 64];    // half2 packed [CINP/2][M]
__device__ unsigned g_Wp2[32 * 128];
__device__ unsigned g_Wp3[64 * 128];
__device__ unsigned g_Wp4[64 * 256];
__device__ float  g_sum[4][256];
__device__ float  g_sq[4][256];
__device__ float  g_sc[4][256];
__device__ float  g_sh[4][256];
__device__ unsigned g_cnt[4];

__device__ __forceinline__ void cp16(void* dst_smem, const void* src) {
    unsigned d = (unsigned)__cvta_generic_to_shared(dst_smem);
    asm volatile("cp.async.cg.shared.global [%0], [%1], 16;" :: "r"(d), "l"(src));
}

// ---------------- depth-ball query (+ zero stats & counters) ----------------
__global__ void k_idx(const float* __restrict__ pc,
                      const float* __restrict__ npc,
                      const int*   __restrict__ qv1)
{
    __shared__ float zs[NPTS];
    __shared__ int   stage[8][32];
    const int b   = blockIdx.x;
    const int tid = threadIdx.x;

    if (b == 0) {
        float* ps = &g_sum[0][0];
        float* pq = &g_sq[0][0];
        for (int i = tid; i < 4 * 256; i += 256) { ps[i] = 0.f; pq[i] = 0.f; }
        if (tid < 4) g_cnt[tid] = 0u;
    }
    for (int i = tid; i < NPTS; i += 256) zs[i] = pc[(b * 3 + 2) * NPTS + i];
    __syncthreads();

    const int w = tid >> 5, lane = tid & 31;
    for (int jj = 0; jj < 32; jj++) {
        const int j = w * 32 + jj;
        const float cz = npc[(b * 3 + 2) * PCTR + j];
        int cnt = 0;
        for (int c = 0; c < NPTS / 32; c++) {
            const int n = c * 32 + lane;
            const bool hit = fabsf(zs[n] - cz) < DIST_;
            const unsigned bal = __ballot_sync(0xffffffffu, hit);
            if (hit) {
                const int pos = cnt + __popc(bal & ((1u << lane) - 1u));
                if (pos < 32) stage[w][pos] = n;
            }
            cnt += __popc(bal);
            if (cnt >= 32) break;
        }
        __syncwarp();
        const int cc = min(cnt, 32);
        const int first = (cnt > 0) ? stage[w][0] : 0;
        const int v = (lane < cc) ? stage[w][lane] : first;
        const int gbase = (b * PCTR + j) * KNB;
        g_idx[gbase + lane]  = v;
        g_ridx[gbase + lane] = qv1[b * NPTS + v];
        if (lane == 0) g_vmask[b * PCTR + j] = (cnt > 0) ? 1.f : 0.f;
        __syncwarp();
    }
}

// ---------------- weight packing ----------------
__device__ __forceinline__ void packW(const float* w, unsigned* dst,
                                      int M, int CIN, int CINP, int tid, int nthr)
{
    const int tot = (CINP / 2) * M;
    for (int i = tid; i < tot; i += nthr) {
        const int p = i / M, m = i - p * M;
        const int k0 = 2 * p, k1 = 2 * p + 1;
        const float a = (k0 < CIN) ? w[m * CIN + k0] : 0.f;
        const float b = (k1 < CIN) ? w[m * CIN + k1] : 0.f;
        __half2 h = __floats2half2_rn(a, b);
        dst[i] = *(unsigned*)&h;
    }
}

__global__ void k_prep(const float* __restrict__ w1, const float* __restrict__ w2,
                       const float* __restrict__ w3, const float* __restrict__ w4)
{
    const int tid = blockIdx.x * blockDim.x + threadIdx.x;
    const int nthr = gridDim.x * blockDim.x;
    packW(w1, g_Wp1, 64, 67, 80, tid, nthr);
    packW(w2, g_Wp2, 128, 64, 64, tid, nthr);
    packW(w3, g_Wp3, 128, 128, 128, tid, nthr);
    packW(w4, g_Wp4, 256, 128, 128, tid, nthr);
}

// ---------------- gather X0 (half) + rgb -> out ----------------
__global__ void k_gather(const float* __restrict__ pc,
                         const float* __restrict__ feat,
                         const float* __restrict__ img1,
                         const float* __restrict__ img2,
                         const float* __restrict__ npc,
                         float* __restrict__ out)
{
    __shared__ int   s_idx[32];
    __shared__ int   s_rid[32];
    __shared__ float s_np[3];
    __shared__ float s_vm;
    const int g = blockIdx.x;
    const int b = g >> 8;
    const int j = g & 255;
    const int t = threadIdx.x;
    const int mbase = g * KNB;

    if (t < 32) { s_idx[t] = g_idx[mbase + t]; s_rid[t] = g_ridx[mbase + t]; }
    if (t >= 32 && t < 35) s_np[t - 32] = npc[(b * 3 + (t - 32)) * PCTR + j];
    if (t == 40) s_vm = g_vmask[g];
    __syncthreads();

    const float vm = s_vm;
    const long ob = (long)b * OUTSTRIDE + (long)j * 32;

    if (t < 96) {
        const int c = t >> 5, k = t & 31;
        g_X0h[c * MTOT + mbase + k] =
            __float2half(pc[(b * 3 + c) * NPTS + s_idx[k]] - s_np[c]);
    }
    for (int e = t; e < INFEA * 32; e += 256) {
        const int c = e >> 5, k = e & 31;
        g_X0h[(3 + c) * MTOT + mbase + k] =
            __float2half(feat[(b * INFEA + c) * NPTS + s_idx[k]]);
    }
    for (int e = t; e < 64 * 32; e += 256) {
        const int c = e >> 5, k = e & 31;
        out[ob + (long)(64 + c) * 8192 + k] = img1[(b * 64 + c) * HW + s_rid[k]] * vm;
    }
    for (int e = t; e < 128 * 32; e += 256) {
        const int c = e >> 5, k = e & 31;
        out[ob + (long)(256 + c) * 8192 + k] = img2[(b * 128 + c) * HW + s_rid[k]] * vm;
    }
}

// ---------------- fp16 TC GEMM: W resident in smem, B double-buffered, 1 sync/iter ----------------
// Y(half)[bm0..bm0+BM) = W @ f(X); fused channel stats + optional fp32 out write of f(X)
// + last-block BN finalize for the whole layer (CTOT channels).
template <int BM, int CTOT, int CIN, bool NORM_IN, int OUTC, int THREADS>
__global__ void __launch_bounds__(THREADS)
k_gemm_h(const unsigned* __restrict__ Wp, const __half* __restrict__ X,
         __half* __restrict__ Y,
         const float* __restrict__ isc, const float* __restrict__ ish,
         float* __restrict__ osum, float* __restrict__ osq,
         float* __restrict__ out,
         const float* __restrict__ gam, const float* __restrict__ bet,
         float* __restrict__ sc, float* __restrict__ sh,
         unsigned* __restrict__ cnt)
{
    constexpr int BN = 128, BK = 16, KP = 8;
    constexpr int NITER = CIN / BK;
    constexpr int WARPS_M = THREADS / 128;      // 4 warps along N
    constexpr int WTM = BM / WARPS_M;
    constexpr int MI = WTM / 16;
    constexpr int KPTOT = CIN / 2;              // total half2 k-pairs
    constexpr int WIT = KPTOT * (BM / 4);       // uint4 items for whole W tile
    constexpr int BIT = KP * (BN / 4);          // uint4 per B stage (=256)
    constexpr int BITER = (BIT + THREADS - 1) / THREADS;

    __shared__ __half2 Ws2[KPTOT][BM + 8];
    __shared__ __half2 Bs2[2][KP][BN + 8];
    __shared__ float redS[BM], redQ[BM];
    __shared__ int s_last;

    const int tid  = threadIdx.x;
    const int lane = tid & 31;
    const int warp = tid >> 5;
    const int wm0  = (warp >> 2) * WTM;
    const int wn0  = (warp & 3) * 32;
    const int bn0  = blockIdx.x * BN;
    const int bm0  = blockIdx.y * BM;
    const int grp  = lane >> 2;
    const int tig  = lane & 3;

    uint4 bReg[BITER];

    // ---- prologue: whole W tile -> smem via cp.async ----
    for (int f = tid; f < WIT; f += THREADS) {
        const int kp = f / (BM / 4), m4 = f % (BM / 4);
        cp16(&Ws2[kp][m4 * 4], &Wp[kp * CTOT + bm0 + m4 * 4]);
    }
    asm volatile("cp.async.commit_group;");

    auto loadB = [&](int k0) {
#pragma unroll
        for (int u = 0; u < BITER; u++) {
            const int e = tid + u * THREADS;
            if (e >= BIT) break;
            const int kk2 = e >> 5;
            const int n = bn0 + (e & 31) * 4;
            const int k = k0 + 2 * kk2;
            const uint2 r0 = *(const uint2*)&X[(size_t)k * MTOT + n];
            const uint2 r1 = *(const uint2*)&X[(size_t)(k + 1) * MTOT + n];
            const __half* h0 = (const __half*)&r0;
            const __half* h1 = (const __half*)&r1;
            float v0[4], v1[4];
#pragma unroll
            for (int j = 0; j < 4; j++) { v0[j] = __half2float(h0[j]); v1[j] = __half2float(h1[j]); }
            if (NORM_IN) {
                const float s0 = isc[k], t0 = ish[k];
                const float s1 = isc[k + 1], t1 = ish[k + 1];
#pragma unroll
                for (int j = 0; j < 4; j++) {
                    v0[j] = fmaxf(v0[j] * s0 + t0, 0.f);
                    v1[j] = fmaxf(v1[j] * s1 + t1, 0.f);
                }
            }
            if (OUTC >= 0) {
                const float vm = g_vmask[n >> 5];
                const int bb = n >> 13, rem = n & 8191;
                float* op = &out[(long)bb * OUTSTRIDE + (long)(OUTC + k) * 8192 + rem];
                *(float4*)op = make_float4(v0[0] * vm, v0[1] * vm, v0[2] * vm, v0[3] * vm);
                op += 8192;
                *(float4*)op = make_float4(v1[0] * vm, v1[1] * vm, v1[2] * vm, v1[3] * vm);
            }
            __half2 h[4];
#pragma unroll
            for (int j = 0; j < 4; j++) h[j] = __floats2half2_rn(v0[j], v1[j]);
            bReg[u] = *(uint4*)h;
        }
    };
    auto storeB = [&](int buf) {
#pragma unroll
        for (int u = 0; u < BITER; u++) {
            const int e = tid + u * THREADS;
            if (e >= BIT) break;
            *(uint4*)&Bs2[buf][e >> 5][(e & 31) * 4] = bReg[u];
        }
    };

    float acc[MI][4][4];
#pragma unroll
    for (int mi = 0; mi < MI; mi++)
#pragma unroll
        for (int ni = 0; ni < 4; ni++)
#pragma unroll
            for (int r = 0; r < 4; r++) acc[mi][ni][r] = 0.f;

    // stage 0 of B + finish W copy
    loadB(0);
    storeB(0);
    asm volatile("cp.async.wait_group 0;");
    __syncthreads();

    for (int it = 0; it < NITER; it++) {
        const int buf = it & 1;
        if (it + 1 < NITER) loadB((it + 1) * BK);

        unsigned a[MI][4], b[4][2];
        const int kpb = it * KP;
#pragma unroll
        for (int mi = 0; mi < MI; mi++) {
            const int row = wm0 + mi * 16 + grp;
            a[mi][0] = *(const unsigned*)&Ws2[kpb + tig][row];
            a[mi][1] = *(const unsigned*)&Ws2[kpb + tig][row + 8];
            a[mi][2] = *(const unsigned*)&Ws2[kpb + tig + 4][row];
            a[mi][3] = *(const unsigned*)&Ws2[kpb + tig + 4][row + 8];
        }
#pragma unroll
        for (int ni = 0; ni < 4; ni++) {
            const int col = wn0 + ni * 8 + grp;
            b[ni][0] = *(const unsigned*)&Bs2[buf][tig][col];
            b[ni][1] = *(const unsigned*)&Bs2[buf][tig + 4][col];
        }
#pragma unroll
        for (int mi = 0; mi < MI; mi++)
#pragma unroll
            for (int ni = 0; ni < 4; ni++) {
                asm volatile(
                    "mma.sync.aligned.m16n8k16.row.col.f32.f16.f16.f32 "
                    "{%0,%1,%2,%3}, {%4,%5,%6,%7}, {%8,%9}, {%0,%1,%2,%3};"
                    : "+f"(acc[mi][ni][0]), "+f"(acc[mi][ni][1]),
                      "+f"(acc[mi][ni][2]), "+f"(acc[mi][ni][3])
                    : "r"(a[mi][0]), "r"(a[mi][1]), "r"(a[mi][2]), "r"(a[mi][3]),
                      "r"(b[ni][0]), "r"(b[ni][1]));
            }
        if (it + 1 < NITER) {
            storeB(buf ^ 1);
            __syncthreads();
        }
    }

    // ---- epilogue: Y(half) + stats ----
    __syncthreads();
    for (int e = tid; e < BM; e += THREADS) { redS[e] = 0.f; redQ[e] = 0.f; }
    __syncthreads();

#pragma unroll
    for (int mi = 0; mi < MI; mi++) {
        const int r1 = wm0 + mi * 16 + grp;
        const int r2 = r1 + 8;
        float s1 = 0.f, q1 = 0.f, s2 = 0.f, q2 = 0.f;
#pragma unroll
        for (int ni = 0; ni < 4; ni++) {
            const int col = bn0 + wn0 + ni * 8 + tig * 2;
            const float c0 = acc[mi][ni][0], c1 = acc[mi][ni][1];
            const float c2 = acc[mi][ni][2], c3 = acc[mi][ni][3];
            *(__half2*)&Y[(size_t)(bm0 + r1) * MTOT + col] = __floats2half2_rn(c0, c1);
            *(__half2*)&Y[(size_t)(bm0 + r2) * MTOT + col] = __floats2half2_rn(c2, c3);
            s1 += c0 + c1;  q1 += c0 * c0 + c1 * c1;
            s2 += c2 + c3;  q2 += c2 * c2 + c3 * c3;
        }
        atomicAdd(&redS[r1], s1);
        atomicAdd(&redQ[r1], q1);
        atomicAdd(&redS[r2], s2);
        atomicAdd(&redQ[r2], q2);
    }
    __syncthreads();
    for (int e = tid; e < BM; e += THREADS) {
        atomicAdd(&osum[bm0 + e], redS[e]);
        atomicAdd(&osq[bm0 + e], redQ[e]);
    }

    // ---- last block finalizes BN scale/shift for the whole layer ----
    __threadfence();
    __syncthreads();
    if (tid == 0) {
        const unsigned done = atomicAdd(cnt, 1u);
        s_last = (done == gridDim.x * gridDim.y - 1) ? 1 : 0;
    }
    __syncthreads();
    if (s_last) {
        __threadfence();
        for (int c = tid; c < CTOT; c += THREADS) {
            const float m = osum[c] * (1.f / (float)MTOT);
            const float v = osq[c] * (1.f / (float)MTOT) - m * m;
            const float s = gam[c] * rsqrtf(v + EPSBN);
            sc[c] = s;
            sh[c] = bet[c] - m * s;
        }
    }
}

// ---------------- final norm_out for Y4 (half in, fp32 out) ----------------
__global__ void k_norm_out_h(const __half* __restrict__ Y, int layer, int C, int cbase,
                             float* __restrict__ out)
{
    const int T = C * (MTOT / 8);
    for (int e = blockIdx.x * blockDim.x + threadIdx.x; e < T;
         e += gridDim.x * blockDim.x) {
        const int c  = e / (MTOT / 8);
        const int m  = (e - c * (MTOT / 8)) * 8;
        const uint4 r = *(const uint4*)&Y[(size_t)c * MTOT + m];
        const __half* h = (const __half*)&r;
        const float s = g_sc[layer][c], t = g_sh[layer][c];
        const float vm = g_vmask[m >> 5];
        const int bb = m >> 13, rem = m & 8191;
        float* op = &out[(long)bb * OUTSTRIDE + (long)(cbase + c) * 8192 + rem];
        float4 o0, o1;
        o0.x = fmaxf(__half2float(h[0]) * s + t, 0.f) * vm;
        o0.y = fmaxf(__half2float(h[1]) * s + t, 0.f) * vm;
        o0.z = fmaxf(__half2float(h[2]) * s + t, 0.f) * vm;
        o0.w = fmaxf(__half2float(h[3]) * s + t, 0.f) * vm;
        o1.x = fmaxf(__half2float(h[4]) * s + t, 0.f) * vm;
        o1.y = fmaxf(__half2float(h[5]) * s + t, 0.f) * vm;
        o1.z = fmaxf(__half2float(h[6]) * s + t, 0.f) * vm;
        o1.w = fmaxf(__half2float(h[7]) * s + t, 0.f) * vm;
        *(float4*)op       = o0;
        *(float4*)(op + 4) = o1;
    }
}

// ---------------- launch ----------------
extern "C" void kernel_launch(void* const* d_in, const int* in_sizes, int n_in,
                              void* d_out, int out_size)
{
    const float* pc   = (const float*)d_in[0];
    const float* feat = (const float*)d_in[1];
    const float* img1 = (const float*)d_in[2];
    const float* img2 = (const float*)d_in[3];
    const int*   qv1  = (const int*)d_in[5];
    const float* npc  = (const float*)d_in[6];
    const float* w1 = (const float*)d_in[7];
    const float* g1 = (const float*)d_in[8];
    const float* b1 = (const float*)d_in[9];
    const float* w2 = (const float*)d_in[10];
    const float* g2 = (const float*)d_in[11];
    const float* b2 = (const float*)d_in[12];
    const float* w3 = (const float*)d_in[13];
    const float* g3 = (const float*)d_in[14];
    const float* b3 = (const float*)d_in[15];
    const float* w4 = (const float*)d_in[16];
    const float* g4 = (const float*)d_in[17];
    const float* b4 = (const float*)d_in[18];
    float* out = (float*)d_out;

    __half *pX0, *pY1, *pY2, *pY3, *pY4;
    unsigned *pW1, *pW2, *pW3, *pW4, *pCnt;
    float *pSum, *pSq, *pSc, *pSh;
    cudaGetSymbolAddress((void**)&pX0, g_X0h);
    cudaGetSymbolAddress((void**)&pY1, g_Y1h);
    cudaGetSymbolAddress((void**)&pY2, g_Y2h);
    cudaGetSymbolAddress((void**)&pY3, g_Y3h);
    cudaGetSymbolAddress((void**)&pY4, g_Y4h);
    cudaGetSymbolAddress((void**)&pW1, g_Wp1);
    cudaGetSymbolAddress((void**)&pW2, g_Wp2);
    cudaGetSymbolAddress((void**)&pW3, g_Wp3);
    cudaGetSymbolAddress((void**)&pW4, g_Wp4);
    cudaGetSymbolAddress((void**)&pSum, g_sum);
    cudaGetSymbolAddress((void**)&pSq,  g_sq);
    cudaGetSymbolAddress((void**)&pSc,  g_sc);
    cudaGetSymbolAddress((void**)&pSh,  g_sh);
    cudaGetSymbolAddress((void**)&pCnt, g_cnt);

    k_idx<<<B_, 256>>>(pc, npc, qv1);
    k_prep<<<32, 256>>>(w1, w2, w3, w4);
    k_gather<<<B_ * PCTR, 256>>>(pc, feat, img1, img2, npc, out);

    const int GX = MTOT / 128;

    // L1: 64 <- 80(pad of 67)
    k_gemm_h<64, 64, 80, false, -1, 256><<<dim3(GX, 1), 256>>>(
        pW1, pX0, pY1, nullptr, nullptr, pSum + 0, pSq + 0, out,
        g1, b1, pSc + 0, pSh + 0, pCnt + 0);
    // L2: 128 <- 64, norm-in(L1), writes bn(Y1) to out ch [0,64)
    k_gemm_h<128, 128, 64, true, 0, 256><<<dim3(GX, 1), 256>>>(
        pW2, pY1, pY2, pSc + 0, pSh + 0, pSum + 256, pSq + 256, out,
        g2, b2, pSc + 256, pSh + 256, pCnt + 1);
    // L3: 128 <- 128, norm-in(L2), writes bn(Y2) to out ch [128,256)
    k_gemm_h<128, 128, 128, true, 128, 256><<<dim3(GX, 1), 256>>>(
        pW3, pY2, pY3, pSc + 256, pSh + 256, pSum + 512, pSq + 512, out,
        g3, b3, pSc + 512, pSh + 512, pCnt + 2);
    // L4: 256 <- 128, norm-in(L3), split over grid.y=2
    k_gemm_h<128, 256, 128, true, -1, 256><<<dim3(GX, 2), 256>>>(
        pW4, pY3, pY4, pSc + 512, pSh + 512, pSum + 768, pSq + 768, out,
        g4, b4, pSc + 768, pSh + 768, pCnt + 3);

    // bn(Y4) -> out ch [384,640)
    k_norm_out_h<<<2048, 256>>>(pY4, 3, 256, 384, out);
}

// round 7
// speedup vs baseline: 1.0368x; 1.0172x over previous
#include <cuda_runtime.h>
#include <cuda_fp16.h>
#include <math.h>

#define B_    16
#define NPTS  2048
#define PCTR  256
#define KNB   32
#define HW    1920
#define INFEA 64
#define MTOT  131072
#define EPSBN 1e-5f
#define DIST_ 0.5f
#define OUTSTRIDE 5242880   // 640*8192

// ---------------- scratch ----------------
__device__ __half g_X0h[80 * MTOT];   // channels 67..79 stay zero
__device__ __half g_Y1h[64 * MTOT];
__device__ __half g_X1n[64 * MTOT];
__device__ __half g_Y2h[128 * MTOT];
__device__ __half g_X2n[128 * MTOT];
__device__ __half g_Y3h[128 * MTOT];
__device__ __half g_X3n[128 * MTOT];
__device__ __half g_Y4h[256 * MTOT];
__device__ int    g_idx[MTOT];
__device__ int    g_ridx[MTOT];
__device__ float  g_vmask[B_ * PCTR];
__device__ __half g_Wp1h[64 * 80];     // row-major [m][k], zero-padded k
__device__ __half g_Wp2h[128 * 64];
__device__ __half g_Wp3h[128 * 128];
__device__ __half g_Wp4h[256 * 128];
__device__ float  g_sum[4][256];
__device__ float  g_sq[4][256];
__device__ float  g_sc[4][256];
__device__ float  g_sh[4][256];
__device__ unsigned g_cnt[4];

__device__ __forceinline__ void cp16(void* dst_smem, const void* src) {
    unsigned d = (unsigned)__cvta_generic_to_shared(dst_smem);
    asm volatile("cp.async.cg.shared.global [%0], [%1], 16;" :: "r"(d), "l"(src));
}
__device__ __forceinline__ void ldsm_x4(unsigned* r, unsigned a) {
    asm volatile("ldmatrix.sync.aligned.m8n8.x4.shared.b16 {%0,%1,%2,%3}, [%4];"
        : "=r"(r[0]), "=r"(r[1]), "=r"(r[2]), "=r"(r[3]) : "r"(a));
}
__device__ __forceinline__ void ldsm_x4_t(unsigned* r, unsigned a) {
    asm volatile("ldmatrix.sync.aligned.m8n8.x4.trans.shared.b16 {%0,%1,%2,%3}, [%4];"
        : "=r"(r[0]), "=r"(r[1]), "=r"(r[2]), "=r"(r[3]) : "r"(a));
}

// ---------------- depth-ball query (+ zero stats & counters) ----------------
__global__ void k_idx(const float* __restrict__ pc,
                      const float* __restrict__ npc,
                      const int*   __restrict__ qv1)
{
    __shared__ float zs[NPTS];
    __shared__ int   stage[8][32];
    const int b   = blockIdx.x;
    const int tid = threadIdx.x;

    if (b == 0) {
        float* ps = &g_sum[0][0];
        float* pq = &g_sq[0][0];
        for (int i = tid; i < 4 * 256; i += 256) { ps[i] = 0.f; pq[i] = 0.f; }
        if (tid < 4) g_cnt[tid] = 0u;
    }
    for (int i = tid; i < NPTS; i += 256) zs[i] = pc[(b * 3 + 2) * NPTS + i];
    __syncthreads();

    const int w = tid >> 5, lane = tid & 31;
    for (int jj = 0; jj < 32; jj++) {
        const int j = w * 32 + jj;
        const float cz = npc[(b * 3 + 2) * PCTR + j];
        int cnt = 0;
        for (int c = 0; c < NPTS / 32; c++) {
            const int n = c * 32 + lane;
            const bool hit = fabsf(zs[n] - cz) < DIST_;
            const unsigned bal = __ballot_sync(0xffffffffu, hit);
            if (hit) {
                const int pos = cnt + __popc(bal & ((1u << lane) - 1u));
                if (pos < 32) stage[w][pos] = n;
            }
            cnt += __popc(bal);
            if (cnt >= 32) break;
        }
        __syncwarp();
        const int cc = min(cnt, 32);
        const int first = (cnt > 0) ? stage[w][0] : 0;
        const int v = (lane < cc) ? stage[w][lane] : first;
        const int gbase = (b * PCTR + j) * KNB;
        g_idx[gbase + lane]  = v;
        g_ridx[gbase + lane] = qv1[b * NPTS + v];
        if (lane == 0) g_vmask[b * PCTR + j] = (cnt > 0) ? 1.f : 0.f;
        __syncwarp();
    }
}

// ---------------- weight packing: row-major [m][k], zero-padded ----------------
__device__ __forceinline__ void packW(const float* w, __half* dst,
                                      int M, int CIN, int CINP, int tid, int nthr)
{
    const int tot = M * CINP;
    for (int i = tid; i < tot; i += nthr) {
        const int m = i / CINP, k = i - m * CINP;
        dst[i] = __float2half((k < CIN) ? w[m * CIN + k] : 0.f);
    }
}

__global__ void k_prep(const float* __restrict__ w1, const float* __restrict__ w2,
                       const float* __restrict__ w3, const float* __restrict__ w4)
{
    const int tid = blockIdx.x * blockDim.x + threadIdx.x;
    const int nthr = gridDim.x * blockDim.x;
    packW(w1, g_Wp1h, 64, 67, 80, tid, nthr);
    packW(w2, g_Wp2h, 128, 64, 64, tid, nthr);
    packW(w3, g_Wp3h, 128, 128, 128, tid, nthr);
    packW(w4, g_Wp4h, 256, 128, 128, tid, nthr);
}

// ---------------- gather X0 (half) + rgb -> out ----------------
__global__ void k_gather(const float* __restrict__ pc,
                         const float* __restrict__ feat,
                         const float* __restrict__ img1,
                         const float* __restrict__ img2,
                         const float* __restrict__ npc,
                         float* __restrict__ out)
{
    __shared__ int   s_idx[32];
    __shared__ int   s_rid[32];
    __shared__ float s_np[3];
    __shared__ float s_vm;
    const int g = blockIdx.x;
    const int b = g >> 8;
    const int j = g & 255;
    const int t = threadIdx.x;
    const int mbase = g * KNB;

    if (t < 32) { s_idx[t] = g_idx[mbase + t]; s_rid[t] = g_ridx[mbase + t]; }
    if (t >= 32 && t < 35) s_np[t - 32] = npc[(b * 3 + (t - 32)) * PCTR + j];
    if (t == 40) s_vm = g_vmask[g];
    __syncthreads();

    const float vm = s_vm;
    const long ob = (long)b * OUTSTRIDE + (long)j * 32;

    if (t < 96) {
        const int c = t >> 5, k = t & 31;
        g_X0h[c * MTOT + mbase + k] =
            __float2half(pc[(b * 3 + c) * NPTS + s_idx[k]] - s_np[c]);
    }
    for (int e = t; e < INFEA * 32; e += 256) {
        const int c = e >> 5, k = e & 31;
        g_X0h[(3 + c) * MTOT + mbase + k] =
            __float2half(feat[(b * INFEA + c) * NPTS + s_idx[k]]);
    }
    for (int e = t; e < 64 * 32; e += 256) {
        const int c = e >> 5, k = e & 31;
        out[ob + (long)(64 + c) * 8192 + k] = img1[(b * 64 + c) * HW + s_rid[k]] * vm;
    }
    for (int e = t; e < 128 * 32; e += 256) {
        const int c = e >> 5, k = e & 31;
        out[ob + (long)(256 + c) * 8192 + k] = img2[(b * 128 + c) * HW + s_rid[k]] * vm;
    }
}

// ---------------- clean fp16 TC GEMM: cp.async 3-stage B, ldmatrix frags ----------------
// Y(half)[bm0..bm0+BM) = W @ X (X pre-normalized); fused channel stats +
// last-block BN finalize for the whole layer (CTOT channels).
template <int BM, int CTOT, int CIN, int THREADS>
__global__ void __launch_bounds__(THREADS)
k_gemm_h(const __half* __restrict__ Wp, const __half* __restrict__ X,
         __half* __restrict__ Y,
         float* __restrict__ osum, float* __restrict__ osq,
         const float* __restrict__ gam, const float* __restrict__ bet,
         float* __restrict__ sc, float* __restrict__ sh,
         unsigned* __restrict__ cnt)
{
    constexpr int BN = 128, BK = 16, PIPE = 3;
    constexpr int NITER = CIN / BK;
    constexpr int WROW = CIN + 8;               // half units; stride mod-8 groups != 0
    constexpr int BROW = BN + 8;
    constexpr int WARPS_M = THREADS / 128;      // 4 warps along N
    constexpr int WTM = BM / WARPS_M;
    constexpr int MI = WTM / 16;
    constexpr int WCH = CIN / 8;                // 16B chunks per W row

    __shared__ __half Ws[BM][WROW];
    __shared__ __half Bs[PIPE][BK][BROW];
    __shared__ int s_last;

    const int tid  = threadIdx.x;
    const int lane = tid & 31;
    const int warp = tid >> 5;
    const int wm0  = (warp >> 2) * WTM;
    const int wn0  = (warp & 3) * 32;
    const int bn0  = blockIdx.x * BN;
    const int bm0  = blockIdx.y * BM;
    const int grp  = lane >> 2;
    const int tig  = lane & 3;

    const unsigned ws_u = (unsigned)__cvta_generic_to_shared(&Ws[0][0]);
    const unsigned bs_u = (unsigned)__cvta_generic_to_shared(&Bs[0][0][0]);

    // ---- prologue: W tile (group 0) ----
    for (int f = tid; f < BM * WCH; f += THREADS) {
        const int m = f / WCH, ch = f % WCH;
        cp16(&Ws[m][ch * 8], &Wp[(size_t)(bm0 + m) * CIN + ch * 8]);
    }
    asm volatile("cp.async.commit_group;");

    auto cpB = [&](int stg, int k0) {
        for (int e = tid; e < BK * (BN / 8); e += THREADS) {
            const int kk = e >> 4, ch = e & 15;
            cp16(&Bs[stg][kk][ch * 8], &X[(size_t)(k0 + kk) * MTOT + bn0 + ch * 8]);
        }
    };
    // stages 0..PIPE-2
#pragma unroll
    for (int s = 0; s < PIPE - 1; s++) {
        if (s < NITER) cpB(s, s * BK);
        asm volatile("cp.async.commit_group;");
    }
    asm volatile("cp.async.wait_group %0;" :: "n"(PIPE - 2));
    __syncthreads();

    float acc[MI][4][4];
#pragma unroll
    for (int mi = 0; mi < MI; mi++)
#pragma unroll
        for (int ni = 0; ni < 4; ni++)
#pragma unroll
            for (int r = 0; r < 4; r++) acc[mi][ni][r] = 0.f;

    // ldmatrix lane addressing pieces
    const int a_row = (lane & 7) + ((lane >> 3) & 1) * 8;   // within 16-row tile
    const int a_kq  = ((lane >> 4) & 1) * 8;                // k + 0/8
    const int b_kr  = ((lane >> 3) & 1) * 8 + (lane & 7);   // k row within stage
    const int b_nq  = ((lane >> 4) & 1) * 8;                // n + 0/8

    for (int it = 0; it < NITER; it++) {
        const int stg = it % PIPE;
        // prefetch stage it+PIPE-1
        if (it + PIPE - 1 < NITER) cpB((it + PIPE - 1) % PIPE, (it + PIPE - 1) * BK);
        asm volatile("cp.async.commit_group;");

        // fragments
        unsigned a[MI][4], bfr[4][2];
#pragma unroll
        for (int mi = 0; mi < MI; mi++) {
            const unsigned addr = ws_u +
                (((wm0 + mi * 16 + a_row) * WROW) + it * BK + a_kq) * 2;
            ldsm_x4(a[mi], addr);
        }
#pragma unroll
        for (int ni2 = 0; ni2 < 2; ni2++) {
            unsigned t4[4];
            const unsigned addr = bs_u + (stg * BK * BROW + b_kr * BROW +
                                          wn0 + ni2 * 16 + b_nq) * 2;
            ldsm_x4_t(t4, addr);
            bfr[ni2 * 2][0] = t4[0]; bfr[ni2 * 2][1] = t4[1];
            bfr[ni2 * 2 + 1][0] = t4[2]; bfr[ni2 * 2 + 1][1] = t4[3];
        }
#pragma unroll
        for (int mi = 0; mi < MI; mi++)
#pragma unroll
            for (int ni = 0; ni < 4; ni++) {
                asm volatile(
                    "mma.sync.aligned.m16n8k16.row.col.f32.f16.f16.f32 "
                    "{%0,%1,%2,%3}, {%4,%5,%6,%7}, {%8,%9}, {%0,%1,%2,%3};"
                    : "+f"(acc[mi][ni][0]), "+f"(acc[mi][ni][1]),
                      "+f"(acc[mi][ni][2]), "+f"(acc[mi][ni][3])
                    : "r"(a[mi][0]), "r"(a[mi][1]), "r"(a[mi][2]), "r"(a[mi][3]),
                      "r"(bfr[ni][0]), "r"(bfr[ni][1]));
            }
        asm volatile("cp.async.wait_group %0;" :: "n"(PIPE - 2));
        __syncthreads();
    }

    // ---- epilogue: Y(half) + stats (reductions alias B smem) ----
    float* redS = (float*)&Bs[0][0][0];
    float* redQ = redS + BM;
    for (int e = tid; e < BM; e += THREADS) { redS[e] = 0.f; redQ[e] = 0.f; }
    __syncthreads();

#pragma unroll
    for (int mi = 0; mi < MI; mi++) {
        const int r1 = wm0 + mi * 16 + grp;
        const int r2 = r1 + 8;
        float s1 = 0.f, q1 = 0.f, s2 = 0.f, q2 = 0.f;
#pragma unroll
        for (int ni = 0; ni < 4; ni++) {
            const int col = bn0 + wn0 + ni * 8 + tig * 2;
            const float c0 = acc[mi][ni][0], c1 = acc[mi][ni][1];
            const float c2 = acc[mi][ni][2], c3 = acc[mi][ni][3];
            *(__half2*)&Y[(size_t)(bm0 + r1) * MTOT + col] = __floats2half2_rn(c0, c1);
            *(__half2*)&Y[(size_t)(bm0 + r2) * MTOT + col] = __floats2half2_rn(c2, c3);
            s1 += c0 + c1;  q1 += c0 * c0 + c1 * c1;
            s2 += c2 + c3;  q2 += c2 * c2 + c3 * c3;
        }
        atomicAdd(&redS[r1], s1);
        atomicAdd(&redQ[r1], q1);
        atomicAdd(&redS[r2], s2);
        atomicAdd(&redQ[r2], q2);
    }
    __syncthreads();
    for (int e = tid; e < BM; e += THREADS) {
        atomicAdd(&osum[bm0 + e], redS[e]);
        atomicAdd(&osq[bm0 + e], redQ[e]);
    }

    // ---- last block finalizes BN scale/shift ----
    __threadfence();
    __syncthreads();
    if (tid == 0) {
        const unsigned done = atomicAdd(cnt, 1u);
        s_last = (done == gridDim.x * gridDim.y - 1) ? 1 : 0;
    }
    __syncthreads();
    if (s_last) {
        __threadfence();
        for (int c = tid; c < CTOT; c += THREADS) {
            const float m = osum[c] * (1.f / (float)MTOT);
            const float v = osq[c] * (1.f / (float)MTOT) - m * m;
            const float s = gam[c] * rsqrtf(v + EPSBN);
            sc[c] = s;
            sh[c] = bet[c] - m * s;
        }
    }
}

// ---------------- norm pass: Xn = relu(s*Y+t) (half), optional fp32 out ----------------
template <bool WX, bool WOUT>
__global__ void k_norm(const __half* __restrict__ Y, int layer, int C, int cbase,
                       __half* __restrict__ Xn, float* __restrict__ out)
{
    const int T = C * (MTOT / 8);
    for (int e = blockIdx.x * blockDim.x + threadIdx.x; e < T;
         e += gridDim.x * blockDim.x) {
        const int c = e / (MTOT / 8);
        const int m = (e - c * (MTOT / 8)) * 8;
        const uint4 r = *(const uint4*)&Y[(size_t)c * MTOT + m];
        const __half* h = (const __half*)&r;
        const float s = g_sc[layer][c], t = g_sh[layer][c];
        float v[8];
#pragma unroll
        for (int j = 0; j < 8; j++)
            v[j] = fmaxf(__half2float(h[j]) * s + t, 0.f);
        if (WX) {
            __half2 o[4];
#pragma unroll
            for (int j = 0; j < 4; j++) o[j] = __floats2half2_rn(v[2 * j], v[2 * j + 1]);
            *(uint4*)&Xn[(size_t)c * MTOT + m] = *(uint4*)o;
        }
        if (WOUT) {
            const float vm = g_vmask[m >> 5];
            const int bb = m >> 13, rem = m & 8191;
            float* op = &out[(long)bb * OUTSTRIDE + (long)(cbase + c) * 8192 + rem];
            *(float4*)op       = make_float4(v[0] * vm, v[1] * vm, v[2] * vm, v[3] * vm);
            *(float4*)(op + 4) = make_float4(v[4] * vm, v[5] * vm, v[6] * vm, v[7] * vm);
        }
    }
}

// ---------------- launch ----------------
extern "C" void kernel_launch(void* const* d_in, const int* in_sizes, int n_in,
                              void* d_out, int out_size)
{
    const float* pc   = (const float*)d_in[0];
    const float* feat = (const float*)d_in[1];
    const float* img1 = (const float*)d_in[2];
    const float* img2 = (const float*)d_in[3];
    const int*   qv1  = (const int*)d_in[5];
    const float* npc  = (const float*)d_in[6];
    const float* w1 = (const float*)d_in[7];
    const float* g1 = (const float*)d_in[8];
    const float* b1 = (const float*)d_in[9];
    const float* w2 = (const float*)d_in[10];
    const float* g2 = (const float*)d_in[11];
    const float* b2 = (const float*)d_in[12];
    const float* w3 = (const float*)d_in[13];
    const float* g3 = (const float*)d_in[14];
    const float* b3 = (const float*)d_in[15];
    const float* w4 = (const float*)d_in[16];
    const float* g4 = (const float*)d_in[17];
    const float* b4 = (const float*)d_in[18];
    float* out = (float*)d_out;

    __half *pX0, *pY1, *pX1, *pY2, *pX2, *pY3, *pX3, *pY4;
    __half *pW1, *pW2, *pW3, *pW4;
    float *pSum, *pSq, *pSc, *pSh;
    unsigned *pCnt;
    cudaGetSymbolAddress((void**)&pX0, g_X0h);
    cudaGetSymbolAddress((void**)&pY1, g_Y1h);
    cudaGetSymbolAddress((void**)&pX1, g_X1n);
    cudaGetSymbolAddress((void**)&pY2, g_Y2h);
    cudaGetSymbolAddress((void**)&pX2, g_X2n);
    cudaGetSymbolAddress((void**)&pY3, g_Y3h);
    cudaGetSymbolAddress((void**)&pX3, g_X3n);
    cudaGetSymbolAddress((void**)&pY4, g_Y4h);
    cudaGetSymbolAddress((void**)&pW1, g_Wp1h);
    cudaGetSymbolAddress((void**)&pW2, g_Wp2h);
    cudaGetSymbolAddress((void**)&pW3, g_Wp3h);
    cudaGetSymbolAddress((void**)&pW4, g_Wp4h);
    cudaGetSymbolAddress((void**)&pSum, g_sum);
    cudaGetSymbolAddress((void**)&pSq,  g_sq);
    cudaGetSymbolAddress((void**)&pSc,  g_sc);
    cudaGetSymbolAddress((void**)&pSh,  g_sh);
    cudaGetSymbolAddress((void**)&pCnt, g_cnt);

    k_idx<<<B_, 256>>>(pc, npc, qv1);
    k_prep<<<32, 256>>>(w1, w2, w3, w4);
    k_gather<<<B_ * PCTR, 256>>>(pc, feat, img1, img2, npc, out);

    const int GX = MTOT / 128;

    // L1: 64 <- 80(pad of 67)
    k_gemm_h<64, 64, 80, 256><<<dim3(GX, 1), 256>>>(
        pW1, pX0, pY1, pSum + 0, pSq + 0, g1, b1, pSc + 0, pSh + 0, pCnt + 0);
    // N1: X1n = f(Y1); out ch [0,64)
    k_norm<true, true><<<4096, 256>>>(pY1, 0, 64, 0, pX1, out);
    // L2: 128 <- 64
    k_gemm_h<128, 128, 64, 256><<<dim3(GX, 1), 256>>>(
        pW2, pX1, pY2, pSum + 256, pSq + 256, g2, b2, pSc + 256, pSh + 256, pCnt + 1);
    // N2: X2n = f(Y2); out ch [128,256)
    k_norm<true, true><<<4096, 256>>>(pY2, 1, 128, 128, pX2, out);
    // L3: 128 <- 128
    k_gemm_h<128, 128, 128, 256><<<dim3(GX, 1), 256>>>(
        pW3, pX2, pY3, pSum + 512, pSq + 512, g3, b3, pSc + 512, pSh + 512, pCnt + 2);
    // N3: X3n = f(Y3) only
    k_norm<true, false><<<4096, 256>>>(pY3, 2, 128, 0, pX3, out);
    // L4: 256 <- 128, grid.y = 2
    k_gemm_h<128, 256, 128, 256><<<dim3(GX, 2), 256>>>(
        pW4, pX3, pY4, pSum + 768, pSq + 768, g4, b4, pSc + 768, pSh + 768, pCnt + 3);
    // N4: out ch [384,640)
    k_norm<false, true><<<4096, 256>>>(pY4, 3, 256, 384, nullptr, out);
}

// round 8
// speedup vs baseline: 1.1793x; 1.1374x over previous
#include <cuda_runtime.h>
#include <cuda_fp16.h>
#include <math.h>

#define B_    16
#define NPTS  2048
#define PCTR  256
#define KNB   32
#define HW    1920
#define INFEA 64
#define MTOT  131072
#define EPSBN 1e-5f
#define DIST_ 0.5f
#define OUTSTRIDE 5242880   // 640*8192

// ---------------- scratch ----------------
__device__ __half g_X0h[80 * MTOT];   // channels 67..79 stay zero
__device__ __half g_Y1h[64 * MTOT];
__device__ __half g_X1n[64 * MTOT];
__device__ __half g_Y2h[128 * MTOT];
__device__ __half g_X2n[128 * MTOT];
__device__ __half g_Y3h[128 * MTOT];
__device__ __half g_X3n[128 * MTOT];
__device__ __half g_Y4h[256 * MTOT];
__device__ int    g_idx[MTOT];
__device__ int    g_ridx[MTOT];
__device__ float  g_vmask[B_ * PCTR];
__device__ __half g_Wp1h[64 * 80];     // row-major [m][k], zero-padded k
__device__ __half g_Wp2h[128 * 64];
__device__ __half g_Wp3h[128 * 128];
__device__ __half g_Wp4h[256 * 128];
__device__ float  g_sum[4][256];
__device__ float  g_sq[4][256];
__device__ float  g_sc[4][256];
__device__ float  g_sh[4][256];
__device__ unsigned g_cnt[4];

__device__ __forceinline__ void cp16(void* dst_smem, const void* src) {
    unsigned d = (unsigned)__cvta_generic_to_shared(dst_smem);
    asm volatile("cp.async.cg.shared.global [%0], [%1], 16;" :: "r"(d), "l"(src));
}
__device__ __forceinline__ void ldsm_x4(unsigned* r, unsigned a) {
    asm volatile("ldmatrix.sync.aligned.m8n8.x4.shared.b16 {%0,%1,%2,%3}, [%4];"
        : "=r"(r[0]), "=r"(r[1]), "=r"(r[2]), "=r"(r[3]) : "r"(a));
}
__device__ __forceinline__ void ldsm_x4_t(unsigned* r, unsigned a) {
    asm volatile("ldmatrix.sync.aligned.m8n8.x4.trans.shared.b16 {%0,%1,%2,%3}, [%4];"
        : "=r"(r[0]), "=r"(r[1]), "=r"(r[2]), "=r"(r[3]) : "r"(a));
}

// ---------------- depth-ball query (+ zero stats & counters) ----------------
__global__ void k_idx(const float* __restrict__ pc,
                      const float* __restrict__ npc,
                      const int*   __restrict__ qv1)
{
    __shared__ float zs[NPTS];
    __shared__ int   stage[8][32];
    const int b   = blockIdx.x;
    const int tid = threadIdx.x;

    if (b == 0) {
        float* ps = &g_sum[0][0];
        float* pq = &g_sq[0][0];
        for (int i = tid; i < 4 * 256; i += 256) { ps[i] = 0.f; pq[i] = 0.f; }
        if (tid < 4) g_cnt[tid] = 0u;
    }
    for (int i = tid; i < NPTS; i += 256) zs[i] = pc[(b * 3 + 2) * NPTS + i];
    __syncthreads();

    const int w = tid >> 5, lane = tid & 31;
    for (int jj = 0; jj < 32; jj++) {
        const int j = w * 32 + jj;
        const float cz = npc[(b * 3 + 2) * PCTR + j];
        int cnt = 0;
        for (int c = 0; c < NPTS / 32; c++) {
            const int n = c * 32 + lane;
            const bool hit = fabsf(zs[n] - cz) < DIST_;
            const unsigned bal = __ballot_sync(0xffffffffu, hit);
            if (hit) {
                const int pos = cnt + __popc(bal & ((1u << lane) - 1u));
                if (pos < 32) stage[w][pos] = n;
            }
            cnt += __popc(bal);
            if (cnt >= 32) break;
        }
        __syncwarp();
        const int cc = min(cnt, 32);
        const int first = (cnt > 0) ? stage[w][0] : 0;
        const int v = (lane < cc) ? stage[w][lane] : first;
        const int gbase = (b * PCTR + j) * KNB;
        g_idx[gbase + lane]  = v;
        g_ridx[gbase + lane] = qv1[b * NPTS + v];
        if (lane == 0) g_vmask[b * PCTR + j] = (cnt > 0) ? 1.f : 0.f;
        __syncwarp();
    }
}

// ---------------- weight packing: row-major [m][k], zero-padded ----------------
__device__ __forceinline__ void packW(const float* w, __half* dst,
                                      int M, int CIN, int CINP, int tid, int nthr)
{
    const int tot = M * CINP;
    for (int i = tid; i < tot; i += nthr) {
        const int m = i / CINP, k = i - m * CINP;
        dst[i] = __float2half((k < CIN) ? w[m * CIN + k] : 0.f);
    }
}

__global__ void k_prep(const float* __restrict__ w1, const float* __restrict__ w2,
                       const float* __restrict__ w3, const float* __restrict__ w4)
{
    const int tid = blockIdx.x * blockDim.x + threadIdx.x;
    const int nthr = gridDim.x * blockDim.x;
    packW(w1, g_Wp1h, 64, 67, 80, tid, nthr);
    packW(w2, g_Wp2h, 128, 64, 64, tid, nthr);
    packW(w3, g_Wp3h, 128, 128, 128, tid, nthr);
    packW(w4, g_Wp4h, 256, 128, 128, tid, nthr);
}

// ---------------- gather X0 (half) + rgb -> out ----------------
__global__ void k_gather(const float* __restrict__ pc,
                         const float* __restrict__ feat,
                         const float* __restrict__ img1,
                         const float* __restrict__ img2,
                         const float* __restrict__ npc,
                         float* __restrict__ out)
{
    __shared__ int   s_idx[32];
    __shared__ int   s_rid[32];
    __shared__ float s_np[3];
    __shared__ float s_vm;
    const int g = blockIdx.x;
    const int b = g >> 8;
    const int j = g & 255;
    const int t = threadIdx.x;
    const int mbase = g * KNB;

    if (t < 32) { s_idx[t] = g_idx[mbase + t]; s_rid[t] = g_ridx[mbase + t]; }
    if (t >= 32 && t < 35) s_np[t - 32] = npc[(b * 3 + (t - 32)) * PCTR + j];
    if (t == 40) s_vm = g_vmask[g];
    __syncthreads();

    const float vm = s_vm;
    const long ob = (long)b * OUTSTRIDE + (long)j * 32;

    if (t < 96) {
        const int c = t >> 5, k = t & 31;
        g_X0h[c * MTOT + mbase + k] =
            __float2half(pc[(b * 3 + c) * NPTS + s_idx[k]] - s_np[c]);
    }
    for (int e = t; e < INFEA * 32; e += 256) {
        const int c = e >> 5, k = e & 31;
        g_X0h[(3 + c) * MTOT + mbase + k] =
            __float2half(feat[(b * INFEA + c) * NPTS + s_idx[k]]);
    }
    for (int e = t; e < 64 * 32; e += 256) {
        const int c = e >> 5, k = e & 31;
        out[ob + (long)(64 + c) * 8192 + k] = img1[(b * 64 + c) * HW + s_rid[k]] * vm;
    }
    for (int e = t; e < 128 * 32; e += 256) {
        const int c = e >> 5, k = e & 31;
        out[ob + (long)(256 + c) * 8192 + k] = img2[(b * 128 + c) * HW + s_rid[k]] * vm;
    }
}

// ---------------- multi-tile fp16 TC GEMM ----------------
// Each block computes TILES consecutive N-tiles of 128 cols; W resident in smem;
// continuous 3-stage cp.async pipeline across tile boundaries; stats in registers,
// one reduction epilogue per block; last block finalizes BN scale/shift.
template <int BM, int CTOT, int CIN, int TILES, int THREADS>
__global__ void __launch_bounds__(THREADS)
k_gemm_h(const __half* __restrict__ Wp, const __half* __restrict__ X,
         __half* __restrict__ Y,
         float* __restrict__ osum, float* __restrict__ osq,
         const float* __restrict__ gam, const float* __restrict__ bet,
         float* __restrict__ sc, float* __restrict__ sh,
         unsigned* __restrict__ cnt)
{
    constexpr int BN = 128, BK = 16, PIPE = 3;
    constexpr int NITER = CIN / BK;
    constexpr int TOT = TILES * NITER;
    constexpr int WROW = CIN + 8;
    constexpr int BROW = BN + 8;
    constexpr int WARPS_M = THREADS / 128;      // 4 warps along N
    constexpr int WTM = BM / WARPS_M;
    constexpr int MI = WTM / 16;
    constexpr int WCH = CIN / 8;

    __shared__ __half Ws[BM][WROW];
    __shared__ __half Bs[PIPE][BK][BROW];
    __shared__ int s_last;

    const int tid  = threadIdx.x;
    const int lane = tid & 31;
    const int warp = tid >> 5;
    const int wm0  = (warp >> 2) * WTM;
    const int wn0  = (warp & 3) * 32;
    const int bn0  = blockIdx.x * (BN * TILES);
    const int bm0  = blockIdx.y * BM;
    const int grp  = lane >> 2;
    const int tig  = lane & 3;

    const unsigned ws_u = (unsigned)__cvta_generic_to_shared(&Ws[0][0]);
    const unsigned bs_u = (unsigned)__cvta_generic_to_shared(&Bs[0][0][0]);

    // W tile (cp.async group 0)
    for (int f = tid; f < BM * WCH; f += THREADS) {
        const int m = f / WCH, ch = f % WCH;
        cp16(&Ws[m][ch * 8], &Wp[(size_t)(bm0 + m) * CIN + ch * 8]);
    }
    asm volatile("cp.async.commit_group;");

    auto cpB = [&](int g) {   // prefetch for flattened iteration g
        const int stg = g % PIPE;
        const int tile = g / NITER, it = g - tile * NITER;
        const int nb = bn0 + tile * BN;
        for (int e = tid; e < BK * (BN / 8); e += THREADS) {
            const int kk = e >> 4, ch = e & 15;
            cp16(&Bs[stg][kk][ch * 8],
                 &X[(size_t)(it * BK + kk) * MTOT + nb + ch * 8]);
        }
    };
#pragma unroll
    for (int s = 0; s < PIPE - 1; s++) {
        if (s < TOT) cpB(s);
        asm volatile("cp.async.commit_group;");
    }
    asm volatile("cp.async.wait_group %0;" :: "n"(PIPE - 2));
    __syncthreads();

    float acc[MI][4][4];
#pragma unroll
    for (int mi = 0; mi < MI; mi++)
#pragma unroll
        for (int ni = 0; ni < 4; ni++)
#pragma unroll
            for (int r = 0; r < 4; r++) acc[mi][ni][r] = 0.f;

    float sS[MI][2], sQ[MI][2];
#pragma unroll
    for (int mi = 0; mi < MI; mi++) {
        sS[mi][0] = sS[mi][1] = 0.f;
        sQ[mi][0] = sQ[mi][1] = 0.f;
    }

    const int a_row = (lane & 7) + ((lane >> 3) & 1) * 8;
    const int a_kq  = ((lane >> 4) & 1) * 8;
    const int b_kr  = ((lane >> 3) & 1) * 8 + (lane & 7);
    const int b_nq  = ((lane >> 4) & 1) * 8;

    for (int g = 0; g < TOT; g++) {
        const int stg = g % PIPE;
        const int tile = g / NITER, it = g - tile * NITER;
        if (g + PIPE - 1 < TOT) cpB(g + PIPE - 1);
        asm volatile("cp.async.commit_group;");

        unsigned a[MI][4], bfr[4][2];
#pragma unroll
        for (int mi = 0; mi < MI; mi++) {
            const unsigned addr = ws_u +
                (((wm0 + mi * 16 + a_row) * WROW) + it * BK + a_kq) * 2;
            ldsm_x4(a[mi], addr);
        }
#pragma unroll
        for (int ni2 = 0; ni2 < 2; ni2++) {
            unsigned t4[4];
            const unsigned addr = bs_u + (stg * BK * BROW + b_kr * BROW +
                                          wn0 + ni2 * 16 + b_nq) * 2;
            ldsm_x4_t(t4, addr);
            bfr[ni2 * 2][0] = t4[0]; bfr[ni2 * 2][1] = t4[1];
            bfr[ni2 * 2 + 1][0] = t4[2]; bfr[ni2 * 2 + 1][1] = t4[3];
        }
#pragma unroll
        for (int mi = 0; mi < MI; mi++)
#pragma unroll
            for (int ni = 0; ni < 4; ni++) {
                asm volatile(
                    "mma.sync.aligned.m16n8k16.row.col.f32.f16.f16.f32 "
                    "{%0,%1,%2,%3}, {%4,%5,%6,%7}, {%8,%9}, {%0,%1,%2,%3};"
                    : "+f"(acc[mi][ni][0]), "+f"(acc[mi][ni][1]),
                      "+f"(acc[mi][ni][2]), "+f"(acc[mi][ni][3])
                    : "r"(a[mi][0]), "r"(a[mi][1]), "r"(a[mi][2]), "r"(a[mi][3]),
                      "r"(bfr[ni][0]), "r"(bfr[ni][1]));
            }

        if (it == NITER - 1) {
            // tile done: write Y, accumulate stats, reset acc
            const int nb = bn0 + tile * BN;
#pragma unroll
            for (int mi = 0; mi < MI; mi++) {
                const int r1 = wm0 + mi * 16 + grp;
                const int r2 = r1 + 8;
#pragma unroll
                for (int ni = 0; ni < 4; ni++) {
                    const int col = nb + wn0 + ni * 8 + tig * 2;
                    const float c0 = acc[mi][ni][0], c1 = acc[mi][ni][1];
                    const float c2 = acc[mi][ni][2], c3 = acc[mi][ni][3];
                    *(__half2*)&Y[(size_t)(bm0 + r1) * MTOT + col] = __floats2half2_rn(c0, c1);
                    *(__half2*)&Y[(size_t)(bm0 + r2) * MTOT + col] = __floats2half2_rn(c2, c3);
                    sS[mi][0] += c0 + c1;  sQ[mi][0] += c0 * c0 + c1 * c1;
                    sS[mi][1] += c2 + c3;  sQ[mi][1] += c2 * c2 + c3 * c3;
                    acc[mi][ni][0] = 0.f; acc[mi][ni][1] = 0.f;
                    acc[mi][ni][2] = 0.f; acc[mi][ni][3] = 0.f;
                }
            }
        }
        asm volatile("cp.async.wait_group %0;" :: "n"(PIPE - 2));
        __syncthreads();
    }

    // ---- epilogue: block stats reduction (aliases B smem) ----
    float* redS = (float*)&Bs[0][0][0];
    float* redQ = redS + BM;
    for (int e = tid; e < BM; e += THREADS) { redS[e] = 0.f; redQ[e] = 0.f; }
    __syncthreads();
#pragma unroll
    for (int mi = 0; mi < MI; mi++) {
        const int r1 = wm0 + mi * 16 + grp;
        atomicAdd(&redS[r1], sS[mi][0]);
        atomicAdd(&redQ[r1], sQ[mi][0]);
        atomicAdd(&redS[r1 + 8], sS[mi][1]);
        atomicAdd(&redQ[r1 + 8], sQ[mi][1]);
    }
    __syncthreads();
    for (int e = tid; e < BM; e += THREADS) {
        atomicAdd(&osum[bm0 + e], redS[e]);
        atomicAdd(&osq[bm0 + e], redQ[e]);
    }

    // ---- last block finalizes BN scale/shift ----
    __threadfence();
    __syncthreads();
    if (tid == 0) {
        const unsigned done = atomicAdd(cnt, 1u);
        s_last = (done == gridDim.x * gridDim.y - 1) ? 1 : 0;
    }
    __syncthreads();
    if (s_last) {
        __threadfence();
        for (int c = tid; c < CTOT; c += THREADS) {
            const float m = osum[c] * (1.f / (float)MTOT);
            const float v = osq[c] * (1.f / (float)MTOT) - m * m;
            const float s = gam[c] * rsqrtf(v + EPSBN);
            sc[c] = s;
            sh[c] = bet[c] - m * s;
        }
    }
}

// ---------------- norm pass: Xn = relu(s*Y+t) (half), optional fp32 out ----------------
template <bool WX, bool WOUT>
__global__ void k_norm(const __half* __restrict__ Y, int layer, int C, int cbase,
                       __half* __restrict__ Xn, float* __restrict__ out)
{
    const int T = C * (MTOT / 8);
    for (int e = blockIdx.x * blockDim.x + threadIdx.x; e < T;
         e += gridDim.x * blockDim.x) {
        const int c = e / (MTOT / 8);
        const int m = (e - c * (MTOT / 8)) * 8;
        const uint4 r = *(const uint4*)&Y[(size_t)c * MTOT + m];
        const __half* h = (const __half*)&r;
        const float s = g_sc[layer][c], t = g_sh[layer][c];
        float v[8];
#pragma unroll
        for (int j = 0; j < 8; j++)
            v[j] = fmaxf(__half2float(h[j]) * s + t, 0.f);
        if (WX) {
            __half2 o[4];
#pragma unroll
            for (int j = 0; j < 4; j++) o[j] = __floats2half2_rn(v[2 * j], v[2 * j + 1]);
            *(uint4*)&Xn[(size_t)c * MTOT + m] = *(uint4*)o;
        }
        if (WOUT) {
            const float vm = g_vmask[m >> 5];
            const int bb = m >> 13, rem = m & 8191;
            float* op = &out[(long)bb * OUTSTRIDE + (long)(cbase + c) * 8192 + rem];
            *(float4*)op       = make_float4(v[0] * vm, v[1] * vm, v[2] * vm, v[3] * vm);
            *(float4*)(op + 4) = make_float4(v[4] * vm, v[5] * vm, v[6] * vm, v[7] * vm);
        }
    }
}

// ---------------- launch ----------------
extern "C" void kernel_launch(void* const* d_in, const int* in_sizes, int n_in,
                              void* d_out, int out_size)
{
    const float* pc   = (const float*)d_in[0];
    const float* feat = (const float*)d_in[1];
    const float* img1 = (const float*)d_in[2];
    const float* img2 = (const float*)d_in[3];
    const int*   qv1  = (const int*)d_in[5];
    const float* npc  = (const float*)d_in[6];
    const float* w1 = (const float*)d_in[7];
    const float* g1 = (const float*)d_in[8];
    const float* b1 = (const float*)d_in[9];
    const float* w2 = (const float*)d_in[10];
    const float* g2 = (const float*)d_in[11];
    const float* b2 = (const float*)d_in[12];
    const float* w3 = (const float*)d_in[13];
    const float* g3 = (const float*)d_in[14];
    const float* b3 = (const float*)d_in[15];
    const float* w4 = (const float*)d_in[16];
    const float* g4 = (const float*)d_in[17];
    const float* b4 = (const float*)d_in[18];
    float* out = (float*)d_out;

    __half *pX0, *pY1, *pX1, *pY2, *pX2, *pY3, *pX3, *pY4;
    __half *pW1, *pW2, *pW3, *pW4;
    float *pSum, *pSq, *pSc, *pSh;
    unsigned *pCnt;
    cudaGetSymbolAddress((void**)&pX0, g_X0h);
    cudaGetSymbolAddress((void**)&pY1, g_Y1h);
    cudaGetSymbolAddress((void**)&pX1, g_X1n);
    cudaGetSymbolAddress((void**)&pY2, g_Y2h);
    cudaGetSymbolAddress((void**)&pX2, g_X2n);
    cudaGetSymbolAddress((void**)&pY3, g_Y3h);
    cudaGetSymbolAddress((void**)&pX3, g_X3n);
    cudaGetSymbolAddress((void**)&pY4, g_Y4h);
    cudaGetSymbolAddress((void**)&pW1, g_Wp1h);
    cudaGetSymbolAddress((void**)&pW2, g_Wp2h);
    cudaGetSymbolAddress((void**)&pW3, g_Wp3h);
    cudaGetSymbolAddress((void**)&pW4, g_Wp4h);
    cudaGetSymbolAddress((void**)&pSum, g_sum);
    cudaGetSymbolAddress((void**)&pSq,  g_sq);
    cudaGetSymbolAddress((void**)&pSc,  g_sc);
    cudaGetSymbolAddress((void**)&pSh,  g_sh);
    cudaGetSymbolAddress((void**)&pCnt, g_cnt);

    k_idx<<<B_, 256>>>(pc, npc, qv1);
    k_prep<<<32, 256>>>(w1, w2, w3, w4);
    k_gather<<<B_ * PCTR, 256>>>(pc, feat, img1, img2, npc, out);

    const int GX = MTOT / (128 * 4);   // 256 blocks, 4 tiles each

    // L1: 64 <- 80(pad of 67)
    k_gemm_h<64, 64, 80, 4, 256><<<dim3(GX, 1), 256>>>(
        pW1, pX0, pY1, pSum + 0, pSq + 0, g1, b1, pSc + 0, pSh + 0, pCnt + 0);
    // N1: X1n = f(Y1); out ch [0,64)
    k_norm<true, true><<<4096, 256>>>(pY1, 0, 64, 0, pX1, out);
    // L2: 128 <- 64
    k_gemm_h<128, 128, 64, 4, 256><<<dim3(GX, 1), 256>>>(
        pW2, pX1, pY2, pSum + 256, pSq + 256, g2, b2, pSc + 256, pSh + 256, pCnt + 1);
    // N2: X2n = f(Y2); out ch [128,256)
    k_norm<true, true><<<4096, 256>>>(pY2, 1, 128, 128, pX2, out);
    // L3: 128 <- 128
    k_gemm_h<128, 128, 128, 4, 256><<<dim3(GX, 1), 256>>>(
        pW3, pX2, pY3, pSum + 512, pSq + 512, g3, b3, pSc + 512, pSh + 512, pCnt + 2);
    // N3: X3n = f(Y3) only
    k_norm<true, false><<<4096, 256>>>(pY3, 2, 128, 0, pX3, out);
    // L4: 256 <- 128, grid.y = 2
    k_gemm_h<128, 256, 128, 4, 256><<<dim3(GX, 2), 256>>>(
        pW4, pX3, pY4, pSum + 768, pSq + 768, g4, b4, pSc + 768, pSh + 768, pCnt + 3);
    // N4: out ch [384,640)
    k_norm<false, true><<<4096, 256>>>(pY4, 3, 256, 384, nullptr, out);
}

// round 9
// speedup vs baseline: 1.2095x; 1.0256x over previous
#include <cuda_runtime.h>
#include <cuda_fp16.h>
#include <math.h>

#define B_    16
#define NPTS  2048
#define PCTR  256
#define KNB   32
#define HW    1920
#define INFEA 64
#define MTOT  131072
#define EPSBN 1e-5f
#define DIST_ 0.5f
#define OUTSTRIDE 5242880   // 640*8192

// ---------------- scratch ----------------
__device__ __half g_X0h[96 * MTOT];   // channels 67..95 stay zero
__device__ __half g_Y1h[64 * MTOT];
__device__ __half g_Y2h[128 * MTOT];
__device__ __half g_Y3h[128 * MTOT];
__device__ __half g_Y4h[256 * MTOT];
__device__ int    g_idx[MTOT];
__device__ int    g_ridx[MTOT];
__device__ float  g_vmask[B_ * PCTR];
__device__ __half g_Wp1h[64 * 96];     // row-major [m][k], zero-padded k
__device__ __half g_Wp2h[128 * 64];
__device__ __half g_Wp3h[128 * 128];
__device__ __half g_Wp4h[256 * 128];
__device__ float  g_sum[4][256];
__device__ float  g_sq[4][256];
__device__ float  g_sc[4][256];
__device__ float  g_sh[4][256];
__device__ __half g_scH[4][256];
__device__ __half g_shH[4][256];
__device__ unsigned g_cnt[4];

__device__ __forceinline__ void cp16(void* dst_smem, const void* src) {
    unsigned d = (unsigned)__cvta_generic_to_shared(dst_smem);
    asm volatile("cp.async.cg.shared.global [%0], [%1], 16;" :: "r"(d), "l"(src));
}
__device__ __forceinline__ void ldsm_x4(unsigned* r, unsigned a) {
    asm volatile("ldmatrix.sync.aligned.m8n8.x4.shared.b16 {%0,%1,%2,%3}, [%4];"
        : "=r"(r[0]), "=r"(r[1]), "=r"(r[2]), "=r"(r[3]) : "r"(a));
}
__device__ __forceinline__ void ldsm_x4_t(unsigned* r, unsigned a) {
    asm volatile("ldmatrix.sync.aligned.m8n8.x4.trans.shared.b16 {%0,%1,%2,%3}, [%4];"
        : "=r"(r[0]), "=r"(r[1]), "=r"(r[2]), "=r"(r[3]) : "r"(a));
}
__device__ __forceinline__ unsigned nrm2(unsigned v, unsigned s, unsigned t) {
    __half2 r = __hfma2(*(__half2*)&v, *(__half2*)&s, *(__half2*)&t);
    r = __hmax2(r, __half2(__half(0.f), __half(0.f)));
    return *(unsigned*)&r;
}

// ---------------- depth-ball query (+ zero stats & counters) ----------------
__global__ void k_idx(const float* __restrict__ pc,
                      const float* __restrict__ npc,
                      const int*   __restrict__ qv1)
{
    __shared__ float zs[NPTS];
    __shared__ int   stage[8][32];
    const int b   = blockIdx.x;
    const int tid = threadIdx.x;

    if (b == 0) {
        float* ps = &g_sum[0][0];
        float* pq = &g_sq[0][0];
        for (int i = tid; i < 4 * 256; i += 256) { ps[i] = 0.f; pq[i] = 0.f; }
        if (tid < 4) g_cnt[tid] = 0u;
    }
    for (int i = tid; i < NPTS; i += 256) zs[i] = pc[(b * 3 + 2) * NPTS + i];
    __syncthreads();

    const int w = tid >> 5, lane = tid & 31;
    for (int jj = 0; jj < 32; jj++) {
        const int j = w * 32 + jj;
        const float cz = npc[(b * 3 + 2) * PCTR + j];
        int cnt = 0;
        for (int c = 0; c < NPTS / 32; c++) {
            const int n = c * 32 + lane;
            const bool hit = fabsf(zs[n] - cz) < DIST_;
            const unsigned bal = __ballot_sync(0xffffffffu, hit);
            if (hit) {
                const int pos = cnt + __popc(bal & ((1u << lane) - 1u));
                if (pos < 32) stage[w][pos] = n;
            }
            cnt += __popc(bal);
            if (cnt >= 32) break;
        }
        __syncwarp();
        const int cc = min(cnt, 32);
        const int first = (cnt > 0) ? stage[w][0] : 0;
        const int v = (lane < cc) ? stage[w][lane] : first;
        const int gbase = (b * PCTR + j) * KNB;
        g_idx[gbase + lane]  = v;
        g_ridx[gbase + lane] = qv1[b * NPTS + v];
        if (lane == 0) g_vmask[b * PCTR + j] = (cnt > 0) ? 1.f : 0.f;
        __syncwarp();
    }
}

// ---------------- weight packing: row-major [m][k], zero-padded ----------------
__device__ __forceinline__ void packW(const float* w, __half* dst,
                                      int M, int CIN, int CINP, int tid, int nthr)
{
    const int tot = M * CINP;
    for (int i = tid; i < tot; i += nthr) {
        const int m = i / CINP, k = i - m * CINP;
        dst[i] = __float2half((k < CIN) ? w[m * CIN + k] : 0.f);
    }
}

__global__ void k_prep(const float* __restrict__ w1, const float* __restrict__ w2,
                       const float* __restrict__ w3, const float* __restrict__ w4)
{
    const int tid = blockIdx.x * blockDim.x + threadIdx.x;
    const int nthr = gridDim.x * blockDim.x;
    packW(w1, g_Wp1h, 64, 67, 96, tid, nthr);
    packW(w2, g_Wp2h, 128, 64, 64, tid, nthr);
    packW(w3, g_Wp3h, 128, 128, 128, tid, nthr);
    packW(w4, g_Wp4h, 256, 128, 128, tid, nthr);
}

// ---------------- gather X0 (half) + rgb -> out ----------------
__global__ void k_gather(const float* __restrict__ pc,
                         const float* __restrict__ feat,
                         const float* __restrict__ img1,
                         const float* __restrict__ img2,
                         const float* __restrict__ npc,
                         float* __restrict__ out)
{
    __shared__ int   s_idx[32];
    __shared__ int   s_rid[32];
    __shared__ float s_np[3];
    __shared__ float s_vm;
    const int g = blockIdx.x;
    const int b = g >> 8;
    const int j = g & 255;
    const int t = threadIdx.x;
    const int mbase = g * KNB;

    if (t < 32) { s_idx[t] = g_idx[mbase + t]; s_rid[t] = g_ridx[mbase + t]; }
    if (t >= 32 && t < 35) s_np[t - 32] = npc[(b * 3 + (t - 32)) * PCTR + j];
    if (t == 40) s_vm = g_vmask[g];
    __syncthreads();

    const float vm = s_vm;
    const long ob = (long)b * OUTSTRIDE + (long)j * 32;

    if (t < 96) {
        const int c = t >> 5, k = t & 31;
        g_X0h[c * MTOT + mbase + k] =
            __float2half(pc[(b * 3 + c) * NPTS + s_idx[k]] - s_np[c]);
    }
    for (int e = t; e < INFEA * 32; e += 256) {
        const int c = e >> 5, k = e & 31;
        g_X0h[(3 + c) * MTOT + mbase + k] =
            __float2half(feat[(b * INFEA + c) * NPTS + s_idx[k]]);
    }
    for (int e = t; e < 64 * 32; e += 256) {
        const int c = e >> 5, k = e & 31;
        out[ob + (long)(64 + c) * 8192 + k] = img1[(b * 64 + c) * HW + s_rid[k]] * vm;
    }
    for (int e = t; e < 128 * 32; e += 256) {
        const int c = e >> 5, k = e & 31;
        out[ob + (long)(256 + c) * 8192 + k] = img2[(b * 128 + c) * HW + s_rid[k]] * vm;
    }
}

// ---------------- multi-tile fp16 TC GEMM, BK=32, fragment-side norm ----------------
// Y(half) = W @ relu(s*X+t) (norm applied on B fragments when NORM_IN);
// X streamed raw via cp.async. Stats in regs; last block finalizes BN (fp32 + half).
template <int BM, int CTOT, int CIN, int TILES, int THREADS, bool NORM_IN>
__global__ void __launch_bounds__(THREADS)
k_gemm_h(const __half* __restrict__ Wp, const __half* __restrict__ X,
         __half* __restrict__ Y,
         const __half* __restrict__ iscH, const __half* __restrict__ ishH,
         float* __restrict__ osum, float* __restrict__ osq,
         const float* __restrict__ gam, const float* __restrict__ bet,
         float* __restrict__ sc, float* __restrict__ sh,
         __half* __restrict__ scH, __half* __restrict__ shH,
         unsigned* __restrict__ cnt)
{
    constexpr int BN = 128, BK = 32, PIPE = 3;
    constexpr int NITER = CIN / BK;
    constexpr int TOT = TILES * NITER;
    constexpr int WROW = CIN + 8;
    constexpr int BROW = BN + 8;
    constexpr int WARPS_M = THREADS / 128;
    constexpr int WTM = BM / WARPS_M;
    constexpr int MI = WTM / 16;
    constexpr int WCH = CIN / 8;

    extern __shared__ __half dsm[];
    __half* Ws = dsm;                               // BM * WROW
    __half* Bs = Ws + BM * WROW;                    // PIPE * BK * BROW
    __half* sS = Bs + PIPE * BK * BROW;             // CIN
    __half* sT = sS + CIN;                          // CIN
    __shared__ int s_last;

    const int tid  = threadIdx.x;
    const int lane = tid & 31;
    const int warp = tid >> 5;
    const int wm0  = (warp >> 2) * WTM;
    const int wn0  = (warp & 3) * 32;
    const int bn0  = blockIdx.x * (BN * TILES);
    const int bm0  = blockIdx.y * BM;
    const int grp  = lane >> 2;
    const int tig  = lane & 3;

    const unsigned ws_u = (unsigned)__cvta_generic_to_shared(Ws);
    const unsigned bs_u = (unsigned)__cvta_generic_to_shared(Bs);

    // W tile + scales (group 0)
    for (int f = tid; f < BM * WCH; f += THREADS) {
        const int m = f / WCH, ch = f % WCH;
        cp16(&Ws[m * WROW + ch * 8], &Wp[(size_t)(bm0 + m) * CIN + ch * 8]);
    }
    if (NORM_IN) {
        for (int e = tid; e < CIN; e += THREADS) { sS[e] = iscH[e]; sT[e] = ishH[e]; }
    }
    asm volatile("cp.async.commit_group;");

    auto cpB = [&](int g) {
        const int stg = g % PIPE;
        const int tile = g / NITER, it = g - tile * NITER;
        const int nb = bn0 + tile * BN;
        for (int e = tid; e < BK * (BN / 8); e += THREADS) {
            const int kk = e >> 4, ch = e & 15;
            cp16(&Bs[(stg * BK + kk) * BROW + ch * 8],
                 &X[(size_t)(it * BK + kk) * MTOT + nb + ch * 8]);
        }
    };
#pragma unroll
    for (int s = 0; s < PIPE - 1; s++) {
        if (s < TOT) cpB(s);
        asm volatile("cp.async.commit_group;");
    }
    asm volatile("cp.async.wait_group %0;" :: "n"(PIPE - 2));
    __syncthreads();

    float acc[MI][4][4];
#pragma unroll
    for (int mi = 0; mi < MI; mi++)
#pragma unroll
        for (int ni = 0; ni < 4; ni++)
#pragma unroll
            for (int r = 0; r < 4; r++) acc[mi][ni][r] = 0.f;

    float sSr[MI][2], sQr[MI][2];
#pragma unroll
    for (int mi = 0; mi < MI; mi++) {
        sSr[mi][0] = sSr[mi][1] = 0.f;
        sQr[mi][0] = sQr[mi][1] = 0.f;
    }

    const int a_row = (lane & 7) + ((lane >> 3) & 1) * 8;
    const int a_kq  = ((lane >> 4) & 1) * 8;
    const int b_kr  = ((lane >> 3) & 1) * 8 + (lane & 7);
    const int b_nq  = ((lane >> 4) & 1) * 8;

    for (int g = 0; g < TOT; g++) {
        const int stg = g % PIPE;
        const int tile = g / NITER, it = g - tile * NITER;
        if (g + PIPE - 1 < TOT) cpB(g + PIPE - 1);
        asm volatile("cp.async.commit_group;");

#pragma unroll
        for (int kk = 0; kk < 2; kk++) {
            const int kbase = it * BK + kk * 16;
            unsigned a[MI][4], bfr[4][2];
#pragma unroll
            for (int mi = 0; mi < MI; mi++) {
                const unsigned addr = ws_u +
                    (((wm0 + mi * 16 + a_row) * WROW) + kbase + a_kq) * 2;
                ldsm_x4(a[mi], addr);
            }
#pragma unroll
            for (int ni2 = 0; ni2 < 2; ni2++) {
                unsigned t4[4];
                const unsigned addr = bs_u + ((stg * BK + kk * 16 + b_kr) * BROW +
                                              wn0 + ni2 * 16 + b_nq) * 2;
                ldsm_x4_t(t4, addr);
                bfr[ni2 * 2][0] = t4[0]; bfr[ni2 * 2][1] = t4[1];
                bfr[ni2 * 2 + 1][0] = t4[2]; bfr[ni2 * 2 + 1][1] = t4[3];
            }
            if (NORM_IN) {
                const int k0 = kbase + 2 * tig;
                const unsigned s0 = *(const unsigned*)&sS[k0];
                const unsigned t0 = *(const unsigned*)&sT[k0];
                const unsigned s1 = *(const unsigned*)&sS[k0 + 8];
                const unsigned t1 = *(const unsigned*)&sT[k0 + 8];
#pragma unroll
                for (int ni = 0; ni < 4; ni++) {
                    bfr[ni][0] = nrm2(bfr[ni][0], s0, t0);
                    bfr[ni][1] = nrm2(bfr[ni][1], s1, t1);
                }
            }
#pragma unroll
            for (int mi = 0; mi < MI; mi++)
#pragma unroll
                for (int ni = 0; ni < 4; ni++) {
                    asm volatile(
                        "mma.sync.aligned.m16n8k16.row.col.f32.f16.f16.f32 "
                        "{%0,%1,%2,%3}, {%4,%5,%6,%7}, {%8,%9}, {%0,%1,%2,%3};"
                        : "+f"(acc[mi][ni][0]), "+f"(acc[mi][ni][1]),
                          "+f"(acc[mi][ni][2]), "+f"(acc[mi][ni][3])
                        : "r"(a[mi][0]), "r"(a[mi][1]), "r"(a[mi][2]), "r"(a[mi][3]),
                          "r"(bfr[ni][0]), "r"(bfr[ni][1]));
                }
        }

        if (it == NITER - 1) {
            const int nb = bn0 + tile * BN;
#pragma unroll
            for (int mi = 0; mi < MI; mi++) {
                const int r1 = wm0 + mi * 16 + grp;
                const int r2 = r1 + 8;
#pragma unroll
                for (int ni = 0; ni < 4; ni++) {
                    const int col = nb + wn0 + ni * 8 + tig * 2;
                    const float c0 = acc[mi][ni][0], c1 = acc[mi][ni][1];
                    const float c2 = acc[mi][ni][2], c3 = acc[mi][ni][3];
                    *(__half2*)&Y[(size_t)(bm0 + r1) * MTOT + col] = __floats2half2_rn(c0, c1);
                    *(__half2*)&Y[(size_t)(bm0 + r2) * MTOT + col] = __floats2half2_rn(c2, c3);
                    sSr[mi][0] += c0 + c1;  sQr[mi][0] += c0 * c0 + c1 * c1;
                    sSr[mi][1] += c2 + c3;  sQr[mi][1] += c2 * c2 + c3 * c3;
                    acc[mi][ni][0] = 0.f; acc[mi][ni][1] = 0.f;
                    acc[mi][ni][2] = 0.f; acc[mi][ni][3] = 0.f;
                }
            }
        }
        asm volatile("cp.async.wait_group %0;" :: "n"(PIPE - 2));
        __syncthreads();
    }

    // ---- epilogue: block stats reduction (aliases B smem) ----
    float* redS = (float*)Bs;
    float* redQ = redS + BM;
    for (int e = tid; e < BM; e += THREADS) { redS[e] = 0.f; redQ[e] = 0.f; }
    __syncthreads();
#pragma unroll
    for (int mi = 0; mi < MI; mi++) {
        const int r1 = wm0 + mi * 16 + grp;
        atomicAdd(&redS[r1], sSr[mi][0]);
        atomicAdd(&redQ[r1], sQr[mi][0]);
        atomicAdd(&redS[r1 + 8], sSr[mi][1]);
        atomicAdd(&redQ[r1 + 8], sQr[mi][1]);
    }
    __syncthreads();
    for (int e = tid; e < BM; e += THREADS) {
        atomicAdd(&osum[bm0 + e], redS[e]);
        atomicAdd(&osq[bm0 + e], redQ[e]);
    }

    // ---- last block finalizes BN scale/shift ----
    __threadfence();
    __syncthreads();
    if (tid == 0) {
        const unsigned done = atomicAdd(cnt, 1u);
        s_last = (done == gridDim.x * gridDim.y - 1) ? 1 : 0;
    }
    __syncthreads();
    if (s_last) {
        __threadfence();
        for (int c = tid; c < CTOT; c += THREADS) {
            const float m = osum[c] * (1.f / (float)MTOT);
            const float v = osq[c] * (1.f / (float)MTOT) - m * m;
            const float s = gam[c] * rsqrtf(v + EPSBN);
            const float t = bet[c] - m * s;
            sc[c] = s;
            sh[c] = t;
            scH[c] = __float2half(s);
            shH[c] = __float2half(t);
        }
    }
}

// ---------------- out writer: out[cbase..cbase+C) = relu(s*Y+t)*vm (fp32) ----------------
__global__ void k_out(const __half* __restrict__ Y, int layer, int C, int cbase,
                      float* __restrict__ out)
{
    const int T = C * (MTOT / 8);
    for (int e = blockIdx.x * blockDim.x + threadIdx.x; e < T;
         e += gridDim.x * blockDim.x) {
        const int c = e / (MTOT / 8);
        const int m = (e - c * (MTOT / 8)) * 8;
        const uint4 r = *(const uint4*)&Y[(size_t)c * MTOT + m];
        const __half* h = (const __half*)&r;
        const float s = g_sc[layer][c], t = g_sh[layer][c];
        const float vm = g_vmask[m >> 5];
        const int bb = m >> 13, rem = m & 8191;
        float* op = &out[(long)bb * OUTSTRIDE + (long)(cbase + c) * 8192 + rem];
        *(float4*)op = make_float4(
            fmaxf(__half2float(h[0]) * s + t, 0.f) * vm,
            fmaxf(__half2float(h[1]) * s + t, 0.f) * vm,
            fmaxf(__half2float(h[2]) * s + t, 0.f) * vm,
            fmaxf(__half2float(h[3]) * s + t, 0.f) * vm);
        *(float4*)(op + 4) = make_float4(
            fmaxf(__half2float(h[4]) * s + t, 0.f) * vm,
            fmaxf(__half2float(h[5]) * s + t, 0.f) * vm,
            fmaxf(__half2float(h[6]) * s + t, 0.f) * vm,
            fmaxf(__half2float(h[7]) * s + t, 0.f) * vm);
    }
}

// ---------------- launch ----------------
extern "C" void kernel_launch(void* const* d_in, const int* in_sizes, int n_in,
                              void* d_out, int out_size)
{
    const float* pc   = (const float*)d_in[0];
    const float* feat = (const float*)d_in[1];
    const float* img1 = (const float*)d_in[2];
    const float* img2 = (const float*)d_in[3];
    const int*   qv1  = (const int*)d_in[5];
    const float* npc  = (const float*)d_in[6];
    const float* w1 = (const float*)d_in[7];
    const float* g1 = (const float*)d_in[8];
    const float* b1 = (const float*)d_in[9];
    const float* w2 = (const float*)d_in[10];
    const float* g2 = (const float*)d_in[11];
    const float* b2 = (const float*)d_in[12];
    const float* w3 = (const float*)d_in[13];
    const float* g3 = (const float*)d_in[14];
    const float* b3 = (const float*)d_in[15];
    const float* w4 = (const float*)d_in[16];
    const float* g4 = (const float*)d_in[17];
    const float* b4 = (const float*)d_in[18];
    float* out = (float*)d_out;

    __half *pX0, *pY1, *pY2, *pY3, *pY4;
    __half *pW1, *pW2, *pW3, *pW4, *pScH, *pShH;
    float *pSum, *pSq, *pSc, *pSh;
    unsigned *pCnt;
    cudaGetSymbolAddress((void**)&pX0, g_X0h);
    cudaGetSymbolAddress((void**)&pY1, g_Y1h);
    cudaGetSymbolAddress((void**)&pY2, g_Y2h);
    cudaGetSymbolAddress((void**)&pY3, g_Y3h);
    cudaGetSymbolAddress((void**)&pY4, g_Y4h);
    cudaGetSymbolAddress((void**)&pW1, g_Wp1h);
    cudaGetSymbolAddress((void**)&pW2, g_Wp2h);
    cudaGetSymbolAddress((void**)&pW3, g_Wp3h);
    cudaGetSymbolAddress((void**)&pW4, g_Wp4h);
    cudaGetSymbolAddress((void**)&pSum, g_sum);
    cudaGetSymbolAddress((void**)&pSq,  g_sq);
    cudaGetSymbolAddress((void**)&pSc,  g_sc);
    cudaGetSymbolAddress((void**)&pSh,  g_sh);
    cudaGetSymbolAddress((void**)&pScH, g_scH);
    cudaGetSymbolAddress((void**)&pShH, g_shH);
    cudaGetSymbolAddress((void**)&pCnt, g_cnt);

    // dynamic smem sizes (bytes)
    auto smemSz = [](int BM, int CIN) {
        return (BM * (CIN + 8) + 3 * 32 * (128 + 8) + 2 * CIN) * 2;
    };
    const int sm1 = smemSz(64, 96);
    const int sm2 = smemSz(128, 64);
    const int sm3 = smemSz(128, 128);

    static bool attr_done = false;
    if (!attr_done) {
        cudaFuncSetAttribute(k_gemm_h<64, 64, 96, 4, 256, false>,
                             cudaFuncAttributeMaxDynamicSharedMemorySize, sm1);
        cudaFuncSetAttribute(k_gemm_h<128, 128, 64, 4, 256, true>,
                             cudaFuncAttributeMaxDynamicSharedMemorySize, sm2);
        cudaFuncSetAttribute(k_gemm_h<128, 128, 128, 4, 256, true>,
                             cudaFuncAttributeMaxDynamicSharedMemorySize, sm3);
        cudaFuncSetAttribute(k_gemm_h<128, 256, 128, 4, 256, true>,
                             cudaFuncAttributeMaxDynamicSharedMemorySize, sm3);
        attr_done = true;
    }

    k_idx<<<B_, 256>>>(pc, npc, qv1);
    k_prep<<<32, 256>>>(w1, w2, w3, w4);
    k_gather<<<B_ * PCTR, 256>>>(pc, feat, img1, img2, npc, out);

    const int GX = MTOT / (128 * 4);   // 256 blocks, 4 tiles each

    // L1: 64 <- 96(pad of 67)
    k_gemm_h<64, 64, 96, 4, 256, false><<<dim3(GX, 1), 256, sm1>>>(
        pW1, pX0, pY1, nullptr, nullptr,
        pSum + 0, pSq + 0, g1, b1, pSc + 0, pSh + 0, pScH + 0, pShH + 0, pCnt + 0);
    // out ch [0,64) from Y1
    k_out<<<2048, 256>>>(pY1, 0, 64, 0, out);
    // L2: 128 <- 64, fragment-norm(L1)
    k_gemm_h<128, 128, 64, 4, 256, true><<<dim3(GX, 1), 256, sm2>>>(
        pW2, pY1, pY2, pScH + 0, pShH + 0,
        pSum + 256, pSq + 256, g2, b2, pSc + 256, pSh + 256, pScH + 256, pShH + 256, pCnt + 1);
    // out ch [128,256) from Y2
    k_out<<<2048, 256>>>(pY2, 1, 128, 128, out);
    // L3: 128 <- 128, fragment-norm(L2)
    k_gemm_h<128, 128, 128, 4, 256, true><<<dim3(GX, 1), 256, sm3>>>(
        pW3, pY2, pY3, pScH + 256, pShH + 256,
        pSum + 512, pSq + 512, g3, b3, pSc + 512, pSh + 512, pScH + 512, pShH + 512, pCnt + 2);
    // L4: 256 <- 128, fragment-norm(L3), grid.y = 2
    k_gemm_h<128, 256, 128, 4, 256, true><<<dim3(GX, 2), 256, sm3>>>(
        pW4, pY3, pY4, pScH + 512, pShH + 512,
        pSum + 768, pSq + 768, g4, b4, pSc + 768, pSh + 768, pScH + 768, pShH + 768, pCnt + 3);
    // out ch [384,640) from Y4
    k_out<<<2048, 256>>>(pY4, 3, 256, 384, out);
}

// round 10
// speedup vs baseline: 1.2242x; 1.0121x over previous
#include <cuda_runtime.h>
#include <cuda_fp16.h>
#include <math.h>

#define B_    16
#define NPTS  2048
#define PCTR  256
#define KNB   32
#define HW    1920
#define INFEA 64
#define MTOT  131072
#define EPSBN 1e-5f
#define DIST_ 0.5f
#define OUTSTRIDE 5242880   // 640*8192

// ---------------- scratch ----------------
__device__ __half g_X0h[96 * MTOT];   // channels 67..95 stay zero
__device__ __half g_Y1h[64 * MTOT];
__device__ __half g_Y2h[128 * MTOT];
__device__ __half g_Y3h[128 * MTOT];
__device__ __half g_Y4h[256 * MTOT];
__device__ int    g_idx[MTOT];
__device__ int    g_ridx[MTOT];
__device__ float  g_vmask[B_ * PCTR];
__device__ __half g_Wp1h[64 * 96];     // row-major [m][k], zero-padded k
__device__ __half g_Wp2h[128 * 64];
__device__ __half g_Wp3h[128 * 128];
__device__ __half g_Wp4h[256 * 128];
__device__ float  g_sum[4][256];
__device__ float  g_sq[4][256];
__device__ float  g_sc[4][256];
__device__ float  g_sh[4][256];
__device__ __half g_scH[4][256];
__device__ __half g_shH[4][256];
__device__ unsigned g_cnt[4];

__device__ __forceinline__ void cp16(void* dst_smem, const void* src) {
    unsigned d = (unsigned)__cvta_generic_to_shared(dst_smem);
    asm volatile("cp.async.cg.shared.global [%0], [%1], 16;" :: "r"(d), "l"(src));
}
__device__ __forceinline__ void ldsm_x4(unsigned* r, unsigned a) {
    asm volatile("ldmatrix.sync.aligned.m8n8.x4.shared.b16 {%0,%1,%2,%3}, [%4];"
        : "=r"(r[0]), "=r"(r[1]), "=r"(r[2]), "=r"(r[3]) : "r"(a));
}
__device__ __forceinline__ void ldsm_x4_t(unsigned* r, unsigned a) {
    asm volatile("ldmatrix.sync.aligned.m8n8.x4.trans.shared.b16 {%0,%1,%2,%3}, [%4];"
        : "=r"(r[0]), "=r"(r[1]), "=r"(r[2]), "=r"(r[3]) : "r"(a));
}
__device__ __forceinline__ unsigned nrm2(unsigned v, unsigned s, unsigned t) {
    __half2 r = __hfma2(*(__half2*)&v, *(__half2*)&s, *(__half2*)&t);
    r = __hmax2(r, __half2(__half(0.f), __half(0.f)));
    return *(unsigned*)&r;
}

// ---------------- depth-ball query (+ zero stats & counters) ----------------
__global__ void k_idx(const float* __restrict__ pc,
                      const float* __restrict__ npc,
                      const int*   __restrict__ qv1)
{
    __shared__ float zs[NPTS];
    __shared__ int   stage[8][32];
    const int b   = blockIdx.x;
    const int tid = threadIdx.x;

    if (b == 0) {
        float* ps = &g_sum[0][0];
        float* pq = &g_sq[0][0];
        for (int i = tid; i < 4 * 256; i += 256) { ps[i] = 0.f; pq[i] = 0.f; }
        if (tid < 4) g_cnt[tid] = 0u;
    }
    for (int i = tid; i < NPTS; i += 256) zs[i] = pc[(b * 3 + 2) * NPTS + i];
    __syncthreads();

    const int w = tid >> 5, lane = tid & 31;
    for (int jj = 0; jj < 32; jj++) {
        const int j = w * 32 + jj;
        const float cz = npc[(b * 3 + 2) * PCTR + j];
        int cnt = 0;
        for (int c = 0; c < NPTS / 32; c++) {
            const int n = c * 32 + lane;
            const bool hit = fabsf(zs[n] - cz) < DIST_;
            const unsigned bal = __ballot_sync(0xffffffffu, hit);
            if (hit) {
                const int pos = cnt + __popc(bal & ((1u << lane) - 1u));
                if (pos < 32) stage[w][pos] = n;
            }
            cnt += __popc(bal);
            if (cnt >= 32) break;
        }
        __syncwarp();
        const int cc = min(cnt, 32);
        const int first = (cnt > 0) ? stage[w][0] : 0;
        const int v = (lane < cc) ? stage[w][lane] : first;
        const int gbase = (b * PCTR + j) * KNB;
        g_idx[gbase + lane]  = v;
        g_ridx[gbase + lane] = qv1[b * NPTS + v];
        if (lane == 0) g_vmask[b * PCTR + j] = (cnt > 0) ? 1.f : 0.f;
        __syncwarp();
    }
}

// ---------------- weight packing ----------------
__device__ __forceinline__ void packW(const float* w, __half* dst,
                                      int M, int CIN, int CINP, int tid, int nthr)
{
    const int tot = M * CINP;
    for (int i = tid; i < tot; i += nthr) {
        const int m = i / CINP, k = i - m * CINP;
        dst[i] = __float2half((k < CIN) ? w[m * CIN + k] : 0.f);
    }
}

__global__ void k_prep(const float* __restrict__ w1, const float* __restrict__ w2,
                       const float* __restrict__ w3, const float* __restrict__ w4)
{
    const int tid = blockIdx.x * blockDim.x + threadIdx.x;
    const int nthr = gridDim.x * blockDim.x;
    packW(w1, g_Wp1h, 64, 67, 96, tid, nthr);
    packW(w2, g_Wp2h, 128, 64, 64, tid, nthr);
    packW(w3, g_Wp3h, 128, 128, 128, tid, nthr);
    packW(w4, g_Wp4h, 256, 128, 128, tid, nthr);
}

// ---------------- gather X0 (half) only ----------------
__global__ void k_gather(const float* __restrict__ pc,
                         const float* __restrict__ feat,
                         const float* __restrict__ npc)
{
    __shared__ int   s_idx[32];
    __shared__ float s_np[3];
    const int g = blockIdx.x;
    const int b = g >> 8;
    const int j = g & 255;
    const int t = threadIdx.x;
    const int mbase = g * KNB;

    if (t < 32) s_idx[t] = g_idx[mbase + t];
    if (t >= 32 && t < 35) s_np[t - 32] = npc[(b * 3 + (t - 32)) * PCTR + j];
    __syncthreads();

    if (t < 96) {
        const int c = t >> 5, k = t & 31;
        g_X0h[c * MTOT + mbase + k] =
            __float2half(pc[(b * 3 + c) * NPTS + s_idx[k]] - s_np[c]);
    }
    for (int e = t; e < INFEA * 32; e += 256) {
        const int c = e >> 5, k = e & 31;
        g_X0h[(3 + c) * MTOT + mbase + k] =
            __float2half(feat[(b * INFEA + c) * NPTS + s_idx[k]]);
    }
}

// ---------------- multi-tile fp16 TC GEMM + embedded writer blocks ----------------
// WMODE 0: pure GEMM. WMODE 1: blocks [GXG, gridDim.x) write out = relu(wsc*wY+wsh)*vm.
// WMODE 2: blocks [GXG, gridDim.x) write rgb1/rgb2 gathers to out.
template <int BM, int CTOT, int CIN, int TILES, int THREADS, bool NORM_IN, int WMODE>
__global__ void __launch_bounds__(THREADS)
k_gemm_h(const __half* __restrict__ Wp, const __half* __restrict__ X,
         __half* __restrict__ Y,
         const __half* __restrict__ iscH, const __half* __restrict__ ishH,
         float* __restrict__ osum, float* __restrict__ osq,
         const float* __restrict__ gam, const float* __restrict__ bet,
         float* __restrict__ sc, float* __restrict__ sh,
         __half* __restrict__ scH, __half* __restrict__ shH,
         unsigned* __restrict__ cnt,
         float* __restrict__ out,
         const __half* __restrict__ wY,
         const float* __restrict__ wsc, const float* __restrict__ wsh,
         const float* __restrict__ wimg1, const float* __restrict__ wimg2,
         int GXG, int ngemm, int wC, int wcbase)
{
    constexpr int BN = 128, BK = 32, PIPE = 3;
    constexpr int NITER = CIN / BK;
    constexpr int TOT = TILES * NITER;
    constexpr int WROW = CIN + 8;
    constexpr int BROW = BN + 8;
    constexpr int WARPS_M = THREADS / 128;
    constexpr int WTM = BM / WARPS_M;
    constexpr int MI = WTM / 16;
    constexpr int WCH = CIN / 8;

    const int tid = threadIdx.x;

    // ---------- embedded writer blocks ----------
    if (WMODE != 0 && (int)blockIdx.x >= GXG) {
        const int wb  = blockIdx.x - GXG;
        const int WBn = gridDim.x - GXG;
        if (WMODE == 1) {
            const int T = wC * (MTOT / 8);
            for (int e = wb * THREADS + tid; e < T; e += WBn * THREADS) {
                const int c = e / (MTOT / 8);
                const int m = (e - c * (MTOT / 8)) * 8;
                const uint4 r = *(const uint4*)&wY[(size_t)c * MTOT + m];
                const __half* h = (const __half*)&r;
                const float s = wsc[c], t = wsh[c];
                const float vm = g_vmask[m >> 5];
                const int bb = m >> 13, rem = m & 8191;
                float* op = &out[(long)bb * OUTSTRIDE + (long)(wcbase + c) * 8192 + rem];
                *(float4*)op = make_float4(
                    fmaxf(__half2float(h[0]) * s + t, 0.f) * vm,
                    fmaxf(__half2float(h[1]) * s + t, 0.f) * vm,
                    fmaxf(__half2float(h[2]) * s + t, 0.f) * vm,
                    fmaxf(__half2float(h[3]) * s + t, 0.f) * vm);
                *(float4*)(op + 4) = make_float4(
                    fmaxf(__half2float(h[4]) * s + t, 0.f) * vm,
                    fmaxf(__half2float(h[5]) * s + t, 0.f) * vm,
                    fmaxf(__half2float(h[6]) * s + t, 0.f) * vm,
                    fmaxf(__half2float(h[7]) * s + t, 0.f) * vm);
            }
        } else {
            const int T = 192 * (MTOT / 4);
            for (int e = wb * THREADS + tid; e < T; e += WBn * THREADS) {
                const int c = e / (MTOT / 4);
                const int m = (e - c * (MTOT / 4)) * 4;
                const int bb = m >> 13;
                const float vm = g_vmask[m >> 5];
                const int4 rid = *(const int4*)&g_ridx[m];
                const float* row;
                int oc;
                if (c < 64) { row = wimg1 + (size_t)(bb * 64 + c) * HW;        oc = 64 + c; }
                else        { row = wimg2 + (size_t)(bb * 128 + (c - 64)) * HW; oc = 256 + (c - 64); }
                float4 o = make_float4(row[rid.x] * vm, row[rid.y] * vm,
                                       row[rid.z] * vm, row[rid.w] * vm);
                *(float4*)&out[(long)bb * OUTSTRIDE + (long)oc * 8192 + (m & 8191)] = o;
            }
        }
        return;
    }

    // ---------- GEMM blocks ----------
    extern __shared__ __half dsm[];
    __half* Ws = dsm;                               // BM * WROW
    __half* Bs = Ws + BM * WROW;                    // PIPE * BK * BROW
    __half* sS = Bs + PIPE * BK * BROW;             // CIN
    __half* sT = sS + CIN;                          // CIN
    __shared__ int s_last;

    const int lane = tid & 31;
    const int warp = tid >> 5;
    const int wm0  = (warp >> 2) * WTM;
    const int wn0  = (warp & 3) * 32;
    const int bn0  = blockIdx.x * (BN * TILES);
    const int bm0  = blockIdx.y * BM;
    const int grp  = lane >> 2;
    const int tig  = lane & 3;

    const unsigned ws_u = (unsigned)__cvta_generic_to_shared(Ws);
    const unsigned bs_u = (unsigned)__cvta_generic_to_shared(Bs);

    for (int f = tid; f < BM * WCH; f += THREADS) {
        const int m = f / WCH, ch = f % WCH;
        cp16(&Ws[m * WROW + ch * 8], &Wp[(size_t)(bm0 + m) * CIN + ch * 8]);
    }
    if (NORM_IN) {
        for (int e = tid; e < CIN; e += THREADS) { sS[e] = iscH[e]; sT[e] = ishH[e]; }
    }
    asm volatile("cp.async.commit_group;");

    auto cpB = [&](int g) {
        const int stg = g % PIPE;
        const int tile = g / NITER, it = g - tile * NITER;
        const int nb = bn0 + tile * BN;
        for (int e = tid; e < BK * (BN / 8); e += THREADS) {
            const int kk = e >> 4, ch = e & 15;
            cp16(&Bs[(stg * BK + kk) * BROW + ch * 8],
                 &X[(size_t)(it * BK + kk) * MTOT + nb + ch * 8]);
        }
    };
#pragma unroll
    for (int s = 0; s < PIPE - 1; s++) {
        if (s < TOT) cpB(s);
        asm volatile("cp.async.commit_group;");
    }
    asm volatile("cp.async.wait_group %0;" :: "n"(PIPE - 2));
    __syncthreads();

    float acc[MI][4][4];
#pragma unroll
    for (int mi = 0; mi < MI; mi++)
#pragma unroll
        for (int ni = 0; ni < 4; ni++)
#pragma unroll
            for (int r = 0; r < 4; r++) acc[mi][ni][r] = 0.f;

    float sSr[MI][2], sQr[MI][2];
#pragma unroll
    for (int mi = 0; mi < MI; mi++) {
        sSr[mi][0] = sSr[mi][1] = 0.f;
        sQr[mi][0] = sQr[mi][1] = 0.f;
    }

    const int a_row = (lane & 7) + ((lane >> 3) & 1) * 8;
    const int a_kq  = ((lane >> 4) & 1) * 8;
    const int b_kr  = ((lane >> 3) & 1) * 8 + (lane & 7);
    const int b_nq  = ((lane >> 4) & 1) * 8;

    for (int g = 0; g < TOT; g++) {
        const int stg = g % PIPE;
        const int tile = g / NITER, it = g - tile * NITER;
        if (g + PIPE - 1 < TOT) cpB(g + PIPE - 1);
        asm volatile("cp.async.commit_group;");

#pragma unroll
        for (int kk = 0; kk < 2; kk++) {
            const int kbase = it * BK + kk * 16;
            unsigned a[MI][4], bfr[4][2];
#pragma unroll
            for (int mi = 0; mi < MI; mi++) {
                const unsigned addr = ws_u +
                    (((wm0 + mi * 16 + a_row) * WROW) + kbase + a_kq) * 2;
                ldsm_x4(a[mi], addr);
            }
#pragma unroll
            for (int ni2 = 0; ni2 < 2; ni2++) {
                unsigned t4[4];
                const unsigned addr = bs_u + ((stg * BK + kk * 16 + b_kr) * BROW +
                                              wn0 + ni2 * 16 + b_nq) * 2;
                ldsm_x4_t(t4, addr);
                bfr[ni2 * 2][0] = t4[0]; bfr[ni2 * 2][1] = t4[1];
                bfr[ni2 * 2 + 1][0] = t4[2]; bfr[ni2 * 2 + 1][1] = t4[3];
            }
            if (NORM_IN) {
                const int k0 = kbase + 2 * tig;
                const unsigned s0 = *(const unsigned*)&sS[k0];
                const unsigned t0 = *(const unsigned*)&sT[k0];
                const unsigned s1 = *(const unsigned*)&sS[k0 + 8];
                const unsigned t1 = *(const unsigned*)&sT[k0 + 8];
#pragma unroll
                for (int ni = 0; ni < 4; ni++) {
                    bfr[ni][0] = nrm2(bfr[ni][0], s0, t0);
                    bfr[ni][1] = nrm2(bfr[ni][1], s1, t1);
                }
            }
#pragma unroll
            for (int mi = 0; mi < MI; mi++)
#pragma unroll
                for (int ni = 0; ni < 4; ni++) {
                    asm volatile(
                        "mma.sync.aligned.m16n8k16.row.col.f32.f16.f16.f32 "
                        "{%0,%1,%2,%3}, {%4,%5,%6,%7}, {%8,%9}, {%0,%1,%2,%3};"
                        : "+f"(acc[mi][ni][0]), "+f"(acc[mi][ni][1]),
                          "+f"(acc[mi][ni][2]), "+f"(acc[mi][ni][3])
                        : "r"(a[mi][0]), "r"(a[mi][1]), "r"(a[mi][2]), "r"(a[mi][3]),
                          "r"(bfr[ni][0]), "r"(bfr[ni][1]));
                }
        }

        if (it == NITER - 1) {
            const int nb = bn0 + tile * BN;
#pragma unroll
            for (int mi = 0; mi < MI; mi++) {
                const int r1 = wm0 + mi * 16 + grp;
                const int r2 = r1 + 8;
#pragma unroll
                for (int ni = 0; ni < 4; ni++) {
                    const int col = nb + wn0 + ni * 8 + tig * 2;
                    const float c0 = acc[mi][ni][0], c1 = acc[mi][ni][1];
                    const float c2 = acc[mi][ni][2], c3 = acc[mi][ni][3];
                    *(__half2*)&Y[(size_t)(bm0 + r1) * MTOT + col] = __floats2half2_rn(c0, c1);
                    *(__half2*)&Y[(size_t)(bm0 + r2) * MTOT + col] = __floats2half2_rn(c2, c3);
                    sSr[mi][0] += c0 + c1;  sQr[mi][0] += c0 * c0 + c1 * c1;
                    sSr[mi][1] += c2 + c3;  sQr[mi][1] += c2 * c2 + c3 * c3;
                    acc[mi][ni][0] = 0.f; acc[mi][ni][1] = 0.f;
                    acc[mi][ni][2] = 0.f; acc[mi][ni][3] = 0.f;
                }
            }
        }
        asm volatile("cp.async.wait_group %0;" :: "n"(PIPE - 2));
        __syncthreads();
    }

    // ---- epilogue: block stats reduction (aliases B smem) ----
    float* redS = (float*)Bs;
    float* redQ = redS + BM;
    for (int e = tid; e < BM; e += THREADS) { redS[e] = 0.f; redQ[e] = 0.f; }
    __syncthreads();
#pragma unroll
    for (int mi = 0; mi < MI; mi++) {
        const int r1 = wm0 + mi * 16 + grp;
        atomicAdd(&redS[r1], sSr[mi][0]);
        atomicAdd(&redQ[r1], sQr[mi][0]);
        atomicAdd(&redS[r1 + 8], sSr[mi][1]);
        atomicAdd(&redQ[r1 + 8], sQr[mi][1]);
    }
    __syncthreads();
    for (int e = tid; e < BM; e += THREADS) {
        atomicAdd(&osum[bm0 + e], redS[e]);
        atomicAdd(&osq[bm0 + e], redQ[e]);
    }

    // ---- last GEMM block finalizes BN scale/shift ----
    __threadfence();
    __syncthreads();
    if (tid == 0) {
        const unsigned done = atomicAdd(cnt, 1u);
        s_last = (done == (unsigned)(ngemm - 1)) ? 1 : 0;
    }
    __syncthreads();
    if (s_last) {
        __threadfence();
        for (int c = tid; c < CTOT; c += THREADS) {
            const float m = osum[c] * (1.f / (float)MTOT);
            const float v = osq[c] * (1.f / (float)MTOT) - m * m;
            const float s = gam[c] * rsqrtf(v + EPSBN);
            const float t = bet[c] - m * s;
            sc[c] = s;
            sh[c] = t;
            scH[c] = __float2half(s);
            shH[c] = __float2half(t);
        }
    }
}

// ---------------- out writer: out[cbase..cbase+C) = relu(s*Y+t)*vm (fp32) ----------------
__global__ void k_out(const __half* __restrict__ Y, int layer, int C, int cbase,
                      float* __restrict__ out)
{
    const int T = C * (MTOT / 8);
    for (int e = blockIdx.x * blockDim.x + threadIdx.x; e < T;
         e += gridDim.x * blockDim.x) {
        const int c = e / (MTOT / 8);
        const int m = (e - c * (MTOT / 8)) * 8;
        const uint4 r = *(const uint4*)&Y[(size_t)c * MTOT + m];
        const __half* h = (const __half*)&r;
        const float s = g_sc[layer][c], t = g_sh[layer][c];
        const float vm = g_vmask[m >> 5];
        const int bb = m >> 13, rem = m & 8191;
        float* op = &out[(long)bb * OUTSTRIDE + (long)(cbase + c) * 8192 + rem];
        *(float4*)op = make_float4(
            fmaxf(__half2float(h[0]) * s + t, 0.f) * vm,
            fmaxf(__half2float(h[1]) * s + t, 0.f) * vm,
            fmaxf(__half2float(h[2]) * s + t, 0.f) * vm,
            fmaxf(__half2float(h[3]) * s + t, 0.f) * vm);
        *(float4*)(op + 4) = make_float4(
            fmaxf(__half2float(h[4]) * s + t, 0.f) * vm,
            fmaxf(__half2float(h[5]) * s + t, 0.f) * vm,
            fmaxf(__half2float(h[6]) * s + t, 0.f) * vm,
            fmaxf(__half2float(h[7]) * s + t, 0.f) * vm);
    }
}

// ---------------- launch ----------------
extern "C" void kernel_launch(void* const* d_in, const int* in_sizes, int n_in,
                              void* d_out, int out_size)
{
    const float* pc   = (const float*)d_in[0];
    const float* feat = (const float*)d_in[1];
    const float* img1 = (const float*)d_in[2];
    const float* img2 = (const float*)d_in[3];
    const int*   qv1  = (const int*)d_in[5];
    const float* npc  = (const float*)d_in[6];
    const float* w1 = (const float*)d_in[7];
    const float* g1 = (const float*)d_in[8];
    const float* b1 = (const float*)d_in[9];
    const float* w2 = (const float*)d_in[10];
    const float* g2 = (const float*)d_in[11];
    const float* b2 = (const float*)d_in[12];
    const float* w3 = (const float*)d_in[13];
    const float* g3 = (const float*)d_in[14];
    const float* b3 = (const float*)d_in[15];
    const float* w4 = (const float*)d_in[16];
    const float* g4 = (const float*)d_in[17];
    const float* b4 = (const float*)d_in[18];
    float* out = (float*)d_out;

    __half *pX0, *pY1, *pY2, *pY3, *pY4;
    __half *pW1, *pW2, *pW3, *pW4, *pScH, *pShH;
    float *pSum, *pSq, *pSc, *pSh;
    unsigned *pCnt;
    cudaGetSymbolAddress((void**)&pX0, g_X0h);
    cudaGetSymbolAddress((void**)&pY1, g_Y1h);
    cudaGetSymbolAddress((void**)&pY2, g_Y2h);
    cudaGetSymbolAddress((void**)&pY3, g_Y3h);
    cudaGetSymbolAddress((void**)&pY4, g_Y4h);
    cudaGetSymbolAddress((void**)&pW1, g_Wp1h);
    cudaGetSymbolAddress((void**)&pW2, g_Wp2h);
    cudaGetSymbolAddress((void**)&pW3, g_Wp3h);
    cudaGetSymbolAddress((void**)&pW4, g_Wp4h);
    cudaGetSymbolAddress((void**)&pSum, g_sum);
    cudaGetSymbolAddress((void**)&pSq,  g_sq);
    cudaGetSymbolAddress((void**)&pSc,  g_sc);
    cudaGetSymbolAddress((void**)&pSh,  g_sh);
    cudaGetSymbolAddress((void**)&pScH, g_scH);
    cudaGetSymbolAddress((void**)&pShH, g_shH);
    cudaGetSymbolAddress((void**)&pCnt, g_cnt);

    auto smemSz = [](int BM, int CIN) {
        return (BM * (CIN + 8) + 3 * 32 * (128 + 8) + 2 * CIN) * 2;
    };
    const int sm1 = smemSz(64, 96);
    const int sm2 = smemSz(128, 64);
    const int sm3 = smemSz(128, 128);

    static bool attr_done = false;
    if (!attr_done) {
        cudaFuncSetAttribute(k_gemm_h<64, 64, 96, 4, 256, false, 2>,
                             cudaFuncAttributeMaxDynamicSharedMemorySize, sm1);
        cudaFuncSetAttribute(k_gemm_h<128, 128, 64, 4, 256, true, 1>,
                             cudaFuncAttributeMaxDynamicSharedMemorySize, sm2);
        cudaFuncSetAttribute(k_gemm_h<128, 128, 128, 4, 256, true, 1>,
                             cudaFuncAttributeMaxDynamicSharedMemorySize, sm3);
        cudaFuncSetAttribute(k_gemm_h<128, 256, 128, 4, 256, true, 0>,
                             cudaFuncAttributeMaxDynamicSharedMemorySize, sm3);
        attr_done = true;
    }

    k_idx<<<B_, 256>>>(pc, npc, qv1);
    k_prep<<<32, 256>>>(w1, w2, w3, w4);
    k_gather<<<B_ * PCTR, 256>>>(pc, feat, npc);

    const int GXG = MTOT / (128 * 4);   // 256 gemm blocks, 4 tiles each
    const int WB  = 256;                // writer blocks appended

    // G1: 64 <- 96(pad of 67); writers: rgb1/rgb2 -> out ch [64,128) & [256,384)
    k_gemm_h<64, 64, 96, 4, 256, false, 2><<<dim3(GXG + WB, 1), 256, sm1>>>(
        pW1, pX0, pY1, nullptr, nullptr,
        pSum + 0, pSq + 0, g1, b1, pSc + 0, pSh + 0, pScH + 0, pShH + 0, pCnt + 0,
        out, nullptr, nullptr, nullptr, img1, img2, GXG, GXG, 0, 0);
    // G2: 128 <- 64, fragment-norm(L1); writers: out ch [0,64) from Y1
    k_gemm_h<128, 128, 64, 4, 256, true, 1><<<dim3(GXG + WB, 1), 256, sm2>>>(
        pW2, pY1, pY2, pScH + 0, pShH + 0,
        pSum + 256, pSq + 256, g2, b2, pSc + 256, pSh + 256, pScH + 256, pShH + 256, pCnt + 1,
        out, pY1, pSc + 0, pSh + 0, nullptr, nullptr, GXG, GXG, 64, 0);
    // G3: 128 <- 128, fragment-norm(L2); writers: out ch [128,256) from Y2
    k_gemm_h<128, 128, 128, 4, 256, true, 1><<<dim3(GXG + WB, 1), 256, sm3>>>(
        pW3, pY2, pY3, pScH + 256, pShH + 256,
        pSum + 512, pSq + 512, g3, b3, pSc + 512, pSh + 512, pScH + 512, pShH + 512, pCnt + 2,
        out, pY2, pSc + 256, pSh + 256, nullptr, nullptr, GXG, GXG, 128, 128);
    // G4: 256 <- 128, fragment-norm(L3), grid.y = 2, no writers
    k_gemm_h<128, 256, 128, 4, 256, true, 0><<<dim3(GXG, 2), 256, sm3>>>(
        pW4, pY3, pY4, pScH + 512, pShH + 512,
        pSum + 768, pSq + 768, g4, b4, pSc + 768, pSh + 768, pScH + 768, pShH + 768, pCnt + 3,
        out, nullptr, nullptr, nullptr, nullptr, nullptr, GXG, GXG * 2, 0, 0);
    // out ch [384,640) from Y4
    k_out<<<2048, 256>>>(pY4, 3, 256, 384, out);
}

// round 11
// speedup vs baseline: 1.2677x; 1.0356x over previous
#include <cuda_runtime.h>
#include <cuda_fp16.h>
#include <math.h>

#define B_    16
#define NPTS  2048
#define PCTR  256
#define KNB   32
#define HW    1920
#define INFEA 64
#define MTOT  131072
#define EPSBN 1e-5f
#define DIST_ 0.5f
#define OUTSTRIDE 5242880   // 640*8192

// ---------------- scratch ----------------
__device__ __half g_X0h[96 * MTOT];   // channels 67..95 stay zero
__device__ __half g_Y1h[64 * MTOT];
__device__ __half g_Y2h[128 * MTOT];
__device__ __half g_Y3h[128 * MTOT];
__device__ __half g_Y4h[256 * MTOT];
__device__ float  g_imgT[B_ * HW * 192];   // pixel-major fused img1+img2
__device__ int    g_idx[MTOT];
__device__ int    g_ridx[MTOT];
__device__ float  g_vmask[B_ * PCTR];
__device__ __half g_Wp1h[64 * 96];
__device__ __half g_Wp2h[128 * 64];
__device__ __half g_Wp3h[128 * 128];
__device__ __half g_Wp4h[256 * 128];
__device__ float  g_sum[4][256];
__device__ float  g_sq[4][256];
__device__ float  g_sc[4][256];
__device__ float  g_sh[4][256];
__device__ __half g_scH[4][256];
__device__ __half g_shH[4][256];
__device__ unsigned g_cnt[4];

__device__ __forceinline__ void cp16(void* dst_smem, const void* src) {
    unsigned d = (unsigned)__cvta_generic_to_shared(dst_smem);
    asm volatile("cp.async.cg.shared.global [%0], [%1], 16;" :: "r"(d), "l"(src));
}
__device__ __forceinline__ void ldsm_x4(unsigned* r, unsigned a) {
    asm volatile("ldmatrix.sync.aligned.m8n8.x4.shared.b16 {%0,%1,%2,%3}, [%4];"
        : "=r"(r[0]), "=r"(r[1]), "=r"(r[2]), "=r"(r[3]) : "r"(a));
}
__device__ __forceinline__ void ldsm_x4_t(unsigned* r, unsigned a) {
    asm volatile("ldmatrix.sync.aligned.m8n8.x4.trans.shared.b16 {%0,%1,%2,%3}, [%4];"
        : "=r"(r[0]), "=r"(r[1]), "=r"(r[2]), "=r"(r[3]) : "r"(a));
}
__device__ __forceinline__ unsigned nrm2(unsigned v, unsigned s, unsigned t) {
    __half2 r = __hfma2(*(__half2*)&v, *(__half2*)&s, *(__half2*)&t);
    r = __hmax2(r, __half2(__half(0.f), __half(0.f)));
    return *(unsigned*)&r;
}

// ---------------- depth-ball query (+ zero stats & counters) ----------------
__global__ void k_idx(const float* __restrict__ pc,
                      const float* __restrict__ npc,
                      const int*   __restrict__ qv1)
{
    __shared__ float zs[NPTS];
    __shared__ int   stage[8][32];
    const int b   = blockIdx.x;
    const int tid = threadIdx.x;

    if (b == 0) {
        float* ps = &g_sum[0][0];
        float* pq = &g_sq[0][0];
        for (int i = tid; i < 4 * 256; i += 256) { ps[i] = 0.f; pq[i] = 0.f; }
        if (tid < 4) g_cnt[tid] = 0u;
    }
    for (int i = tid; i < NPTS; i += 256) zs[i] = pc[(b * 3 + 2) * NPTS + i];
    __syncthreads();

    const int w = tid >> 5, lane = tid & 31;
    for (int jj = 0; jj < 32; jj++) {
        const int j = w * 32 + jj;
        const float cz = npc[(b * 3 + 2) * PCTR + j];
        int cnt = 0;
        for (int c = 0; c < NPTS / 32; c++) {
            const int n = c * 32 + lane;
            const bool hit = fabsf(zs[n] - cz) < DIST_;
            const unsigned bal = __ballot_sync(0xffffffffu, hit);
            if (hit) {
                const int pos = cnt + __popc(bal & ((1u << lane) - 1u));
                if (pos < 32) stage[w][pos] = n;
            }
            cnt += __popc(bal);
            if (cnt >= 32) break;
        }
        __syncwarp();
        const int cc = min(cnt, 32);
        const int first = (cnt > 0) ? stage[w][0] : 0;
        const int v = (lane < cc) ? stage[w][lane] : first;
        const int gbase = (b * PCTR + j) * KNB;
        g_idx[gbase + lane]  = v;
        g_ridx[gbase + lane] = qv1[b * NPTS + v];
        if (lane == 0) g_vmask[b * PCTR + j] = (cnt > 0) ? 1.f : 0.f;
        __syncwarp();
    }
}

// ---------------- weight packing ----------------
__device__ __forceinline__ void packW(const float* w, __half* dst,
                                      int M, int CIN, int CINP, int tid, int nthr)
{
    const int tot = M * CINP;
    for (int i = tid; i < tot; i += nthr) {
        const int m = i / CINP, k = i - m * CINP;
        dst[i] = __float2half((k < CIN) ? w[m * CIN + k] : 0.f);
    }
}

__global__ void k_prep(const float* __restrict__ w1, const float* __restrict__ w2,
                       const float* __restrict__ w3, const float* __restrict__ w4)
{
    const int tid = blockIdx.x * blockDim.x + threadIdx.x;
    const int nthr = gridDim.x * blockDim.x;
    packW(w1, g_Wp1h, 64, 67, 96, tid, nthr);
    packW(w2, g_Wp2h, 128, 64, 64, tid, nthr);
    packW(w3, g_Wp3h, 128, 128, 128, tid, nthr);
    packW(w4, g_Wp4h, 256, 128, 128, tid, nthr);
}

// ---------------- img transpose: [B][C][HW] -> [B][HW][192] ----------------
__global__ void k_timg(const float* __restrict__ img1, const float* __restrict__ img2)
{
    __shared__ float tile[32][33];
    const int b  = blockIdx.z;
    const int p0 = blockIdx.x * 32;
    const int c0 = blockIdx.y * 32;
    const int tx = threadIdx.x, ty = threadIdx.y;

    const int c = c0 + ty;
    const float* src = (c < 64) ? &img1[(size_t)(b * 64 + c) * HW]
                                : &img2[(size_t)(b * 128 + (c - 64)) * HW];
    tile[ty][tx] = src[p0 + tx];
    __syncthreads();
    g_imgT[((size_t)b * HW + p0 + ty) * 192 + c0 + tx] = tile[tx][ty];
}

// ---------------- gather X0 (half) only ----------------
__global__ void k_gather(const float* __restrict__ pc,
                         const float* __restrict__ feat,
                         const float* __restrict__ npc)
{
    __shared__ int   s_idx[32];
    __shared__ float s_np[3];
    const int g = blockIdx.x;
    const int b = g >> 8;
    const int j = g & 255;
    const int t = threadIdx.x;
    const int mbase = g * KNB;

    if (t < 32) s_idx[t] = g_idx[mbase + t];
    if (t >= 32 && t < 35) s_np[t - 32] = npc[(b * 3 + (t - 32)) * PCTR + j];
    __syncthreads();

    if (t < 96) {
        const int c = t >> 5, k = t & 31;
        g_X0h[c * MTOT + mbase + k] =
            __float2half(pc[(b * 3 + c) * NPTS + s_idx[k]] - s_np[c]);
    }
    for (int e = t; e < INFEA * 32; e += 256) {
        const int c = e >> 5, k = e & 31;
        g_X0h[(3 + c) * MTOT + mbase + k] =
            __float2half(feat[(b * INFEA + c) * NPTS + s_idx[k]]);
    }
}

// ---------------- multi-tile fp16 TC GEMM + embedded writer blocks ----------------
// WMODE 0: pure GEMM. WMODE 1: writers emit out = relu(wsc*wY+wsh)*vm.
// WMODE 2: writers emit rgb1/rgb2 from pixel-major imgT (coalesced).
template <int BM, int CTOT, int CIN, int TILES, int THREADS, bool NORM_IN, int WMODE>
__global__ void __launch_bounds__(THREADS)
k_gemm_h(const __half* __restrict__ Wp, const __half* __restrict__ X,
         __half* __restrict__ Y,
         const __half* __restrict__ iscH, const __half* __restrict__ ishH,
         float* __restrict__ osum, float* __restrict__ osq,
         const float* __restrict__ gam, const float* __restrict__ bet,
         float* __restrict__ sc, float* __restrict__ sh,
         __half* __restrict__ scH, __half* __restrict__ shH,
         unsigned* __restrict__ cnt,
         float* __restrict__ out,
         const __half* __restrict__ wY,
         const float* __restrict__ wsc, const float* __restrict__ wsh,
         const float* __restrict__ imgT,
         int GXG, int ngemm, int wC, int wcbase)
{
    constexpr int BN = 128, BK = 32, PIPE = 3;
    constexpr int NITER = CIN / BK;
    constexpr int TOT = TILES * NITER;
    constexpr int WROW = CIN + 8;
    constexpr int BROW = BN + 8;
    constexpr int WARPS_M = THREADS / 128;
    constexpr int WTM = BM / WARPS_M;
    constexpr int MI = WTM / 16;
    constexpr int WCH = CIN / 8;

    const int tid = threadIdx.x;
    extern __shared__ __half dsm[];

    // ---------- embedded writer blocks ----------
    if (WMODE != 0 && (int)blockIdx.x >= GXG) {
        const int wb  = blockIdx.x - GXG;
        const int WBn = gridDim.x - GXG;
        if (WMODE == 1) {
            const int T = wC * (MTOT / 8);
            for (int e = wb * THREADS + tid; e < T; e += WBn * THREADS) {
                const int c = e / (MTOT / 8);
                const int m = (e - c * (MTOT / 8)) * 8;
                const uint4 r = *(const uint4*)&wY[(size_t)c * MTOT + m];
                const __half* h = (const __half*)&r;
                const float s = wsc[c], t = wsh[c];
                const float vm = g_vmask[m >> 5];
                const int bb = m >> 13, rem = m & 8191;
                float* op = &out[(long)bb * OUTSTRIDE + (long)(wcbase + c) * 8192 + rem];
                *(float4*)op = make_float4(
                    fmaxf(__half2float(h[0]) * s + t, 0.f) * vm,
                    fmaxf(__half2float(h[1]) * s + t, 0.f) * vm,
                    fmaxf(__half2float(h[2]) * s + t, 0.f) * vm,
                    fmaxf(__half2float(h[3]) * s + t, 0.f) * vm);
                *(float4*)(op + 4) = make_float4(
                    fmaxf(__half2float(h[4]) * s + t, 0.f) * vm,
                    fmaxf(__half2float(h[5]) * s + t, 0.f) * vm,
                    fmaxf(__half2float(h[6]) * s + t, 0.f) * vm,
                    fmaxf(__half2float(h[7]) * s + t, 0.f) * vm);
            }
        } else {
            // rgb writer: coalesced rows from imgT, smem-staged transpose to out
            float* sm = (float*)dsm;                 // [192][33] stage
            int*   rp = (int*)(sm + 192 * 33);       // 32 pixel ids
            float* vmp = sm + 192 * 33 + 32;
            for (int g0 = wb; g0 < B_ * PCTR; g0 += WBn) {
                const int b = g0 >> 8, j = g0 & 255;
                if (tid < 32) rp[tid] = g_ridx[g0 * KNB + tid];
                if (tid == 32) vmp[0] = g_vmask[g0];
                __syncthreads();
                const float vm = vmp[0];
                for (int e = tid; e < 32 * 48; e += THREADS) {
                    const int k = e / 48, c4 = e - k * 48;
                    const float4 v =
                        ((const float4*)&imgT[((size_t)b * HW + rp[k]) * 192])[c4];
                    sm[(c4 * 4 + 0) * 33 + k] = v.x;
                    sm[(c4 * 4 + 1) * 33 + k] = v.y;
                    sm[(c4 * 4 + 2) * 33 + k] = v.z;
                    sm[(c4 * 4 + 3) * 33 + k] = v.w;
                }
                __syncthreads();
                const long ob = (long)b * OUTSTRIDE + (long)j * 32;
                for (int e = tid; e < 192 * 8; e += THREADS) {
                    const int c = e >> 3, q = e & 7;
                    const int oc = (c < 64) ? 64 + c : 192 + c;   // 256+(c-64)
                    const float* sp = &sm[c * 33 + q * 4];
                    float4 o = make_float4(sp[0] * vm, sp[1] * vm, sp[2] * vm, sp[3] * vm);
                    *(float4*)&out[ob + (long)oc * 8192 + q * 4] = o;
                }
                __syncthreads();
            }
        }
        return;
    }

    // ---------- GEMM blocks ----------
    __half* Ws = dsm;                               // BM * WROW
    __half* Bs = Ws + BM * WROW;                    // PIPE * BK * BROW
    __half* sS = Bs + PIPE * BK * BROW;             // CIN
    __half* sT = sS + CIN;                          // CIN
    __shared__ int s_last;

    const int lane = tid & 31;
    const int warp = tid >> 5;
    const int wm0  = (warp >> 2) * WTM;
    const int wn0  = (warp & 3) * 32;
    const int bn0  = blockIdx.x * (BN * TILES);
    const int bm0  = blockIdx.y * BM;
    const int grp  = lane >> 2;
    const int tig  = lane & 3;

    const unsigned ws_u = (unsigned)__cvta_generic_to_shared(Ws);
    const unsigned bs_u = (unsigned)__cvta_generic_to_shared(Bs);

    for (int f = tid; f < BM * WCH; f += THREADS) {
        const int m = f / WCH, ch = f % WCH;
        cp16(&Ws[m * WROW + ch * 8], &Wp[(size_t)(bm0 + m) * CIN + ch * 8]);
    }
    if (NORM_IN) {
        for (int e = tid; e < CIN; e += THREADS) { sS[e] = iscH[e]; sT[e] = ishH[e]; }
    }
    asm volatile("cp.async.commit_group;");

    auto cpB = [&](int g) {
        const int stg = g % PIPE;
        const int tile = g / NITER, it = g - tile * NITER;
        const int nb = bn0 + tile * BN;
        for (int e = tid; e < BK * (BN / 8); e += THREADS) {
            const int kk = e >> 4, ch = e & 15;
            cp16(&Bs[(stg * BK + kk) * BROW + ch * 8],
                 &X[(size_t)(it * BK + kk) * MTOT + nb + ch * 8]);
        }
    };
#pragma unroll
    for (int s = 0; s < PIPE - 1; s++) {
        if (s < TOT) cpB(s);
        asm volatile("cp.async.commit_group;");
    }
    asm volatile("cp.async.wait_group %0;" :: "n"(PIPE - 2));
    __syncthreads();

    float acc[MI][4][4];
#pragma unroll
    for (int mi = 0; mi < MI; mi++)
#pragma unroll
        for (int ni = 0; ni < 4; ni++)
#pragma unroll
            for (int r = 0; r < 4; r++) acc[mi][ni][r] = 0.f;

    float sSr[MI][2], sQr[MI][2];
#pragma unroll
    for (int mi = 0; mi < MI; mi++) {
        sSr[mi][0] = sSr[mi][1] = 0.f;
        sQr[mi][0] = sQr[mi][1] = 0.f;
    }

    const int a_row = (lane & 7) + ((lane >> 3) & 1) * 8;
    const int a_kq  = ((lane >> 4) & 1) * 8;
    const int b_kr  = ((lane >> 3) & 1) * 8 + (lane & 7);
    const int b_nq  = ((lane >> 4) & 1) * 8;

    for (int g = 0; g < TOT; g++) {
        const int stg = g % PIPE;
        const int tile = g / NITER, it = g - tile * NITER;
        if (g + PIPE - 1 < TOT) cpB(g + PIPE - 1);
        asm volatile("cp.async.commit_group;");

#pragma unroll
        for (int kk = 0; kk < 2; kk++) {
            const int kbase = it * BK + kk * 16;
            unsigned a[MI][4], bfr[4][2];
#pragma unroll
            for (int mi = 0; mi < MI; mi++) {
                const unsigned addr = ws_u +
                    (((wm0 + mi * 16 + a_row) * WROW) + kbase + a_kq) * 2;
                ldsm_x4(a[mi], addr);
            }
#pragma unroll
            for (int ni2 = 0; ni2 < 2; ni2++) {
                unsigned t4[4];
                const unsigned addr = bs_u + ((stg * BK + kk * 16 + b_kr) * BROW +
                                              wn0 + ni2 * 16 + b_nq) * 2;
                ldsm_x4_t(t4, addr);
                bfr[ni2 * 2][0] = t4[0]; bfr[ni2 * 2][1] = t4[1];
                bfr[ni2 * 2 + 1][0] = t4[2]; bfr[ni2 * 2 + 1][1] = t4[3];
            }
            if (NORM_IN) {
                const int k0 = kbase + 2 * tig;
                const unsigned s0 = *(const unsigned*)&sS[k0];
                const unsigned t0 = *(const unsigned*)&sT[k0];
                const unsigned s1 = *(const unsigned*)&sS[k0 + 8];
                const unsigned t1 = *(const unsigned*)&sT[k0 + 8];
#pragma unroll
                for (int ni = 0; ni < 4; ni++) {
                    bfr[ni][0] = nrm2(bfr[ni][0], s0, t0);
                    bfr[ni][1] = nrm2(bfr[ni][1], s1, t1);
                }
            }
#pragma unroll
            for (int mi = 0; mi < MI; mi++)
#pragma unroll
                for (int ni = 0; ni < 4; ni++) {
                    asm volatile(
                        "mma.sync.aligned.m16n8k16.row.col.f32.f16.f16.f32 "
                        "{%0,%1,%2,%3}, {%4,%5,%6,%7}, {%8,%9}, {%0,%1,%2,%3};"
                        : "+f"(acc[mi][ni][0]), "+f"(acc[mi][ni][1]),
                          "+f"(acc[mi][ni][2]), "+f"(acc[mi][ni][3])
                        : "r"(a[mi][0]), "r"(a[mi][1]), "r"(a[mi][2]), "r"(a[mi][3]),
                          "r"(bfr[ni][0]), "r"(bfr[ni][1]));
                }
        }

        if (it == NITER - 1) {
            const int nb = bn0 + tile * BN;
#pragma unroll
            for (int mi = 0; mi < MI; mi++) {
                const int r1 = wm0 + mi * 16 + grp;
                const int r2 = r1 + 8;
#pragma unroll
                for (int ni = 0; ni < 4; ni++) {
                    const int col = nb + wn0 + ni * 8 + tig * 2;
                    const float c0 = acc[mi][ni][0], c1 = acc[mi][ni][1];
                    const float c2 = acc[mi][ni][2], c3 = acc[mi][ni][3];
                    *(__half2*)&Y[(size_t)(bm0 + r1) * MTOT + col] = __floats2half2_rn(c0, c1);
                    *(__half2*)&Y[(size_t)(bm0 + r2) * MTOT + col] = __floats2half2_rn(c2, c3);
                    sSr[mi][0] += c0 + c1;  sQr[mi][0] += c0 * c0 + c1 * c1;
                    sSr[mi][1] += c2 + c3;  sQr[mi][1] += c2 * c2 + c3 * c3;
                    acc[mi][ni][0] = 0.f; acc[mi][ni][1] = 0.f;
                    acc[mi][ni][2] = 0.f; acc[mi][ni][3] = 0.f;
                }
            }
        }
        asm volatile("cp.async.wait_group %0;" :: "n"(PIPE - 2));
        __syncthreads();
    }

    // ---- epilogue: block stats reduction (aliases B smem) ----
    float* redS = (float*)Bs;
    float* redQ = redS + BM;
    for (int e = tid; e < BM; e += THREADS) { redS[e] = 0.f; redQ[e] = 0.f; }
    __syncthreads();
#pragma unroll
    for (int mi = 0; mi < MI; mi++) {
        const int r1 = wm0 + mi * 16 + grp;
        atomicAdd(&redS[r1], sSr[mi][0]);
        atomicAdd(&redQ[r1], sQr[mi][0]);
        atomicAdd(&redS[r1 + 8], sSr[mi][1]);
        atomicAdd(&redQ[r1 + 8], sQr[mi][1]);
    }
    __syncthreads();
    for (int e = tid; e < BM; e += THREADS) {
        atomicAdd(&osum[bm0 + e], redS[e]);
        atomicAdd(&osq[bm0 + e], redQ[e]);
    }

    // ---- last GEMM block finalizes BN scale/shift ----
    __threadfence();
    __syncthreads();
    if (tid == 0) {
        const unsigned done = atomicAdd(cnt, 1u);
        s_last = (done == (unsigned)(ngemm - 1)) ? 1 : 0;
    }
    __syncthreads();
    if (s_last) {
        __threadfence();
        for (int c = tid; c < CTOT; c += THREADS) {
            const float m = osum[c] * (1.f / (float)MTOT);
            const float v = osq[c] * (1.f / (float)MTOT) - m * m;
            const float s = gam[c] * rsqrtf(v + EPSBN);
            const float t = bet[c] - m * s;
            sc[c] = s;
            sh[c] = t;
            scH[c] = __float2half(s);
            shH[c] = __float2half(t);
        }
    }
}

// ---------------- out writer: out[cbase..cbase+C) = relu(s*Y+t)*vm (fp32) ----------------
__global__ void k_out(const __half* __restrict__ Y, int layer, int C, int cbase,
                      float* __restrict__ out)
{
    const int T = C * (MTOT / 8);
    for (int e = blockIdx.x * blockDim.x + threadIdx.x; e < T;
         e += gridDim.x * blockDim.x) {
        const int c = e / (MTOT / 8);
        const int m = (e - c * (MTOT / 8)) * 8;
        const uint4 r = *(const uint4*)&Y[(size_t)c * MTOT + m];
        const __half* h = (const __half*)&r;
        const float s = g_sc[layer][c], t = g_sh[layer][c];
        const float vm = g_vmask[m >> 5];
        const int bb = m >> 13, rem = m & 8191;
        float* op = &out[(long)bb * OUTSTRIDE + (long)(cbase + c) * 8192 + rem];
        *(float4*)op = make_float4(
            fmaxf(__half2float(h[0]) * s + t, 0.f) * vm,
            fmaxf(__half2float(h[1]) * s + t, 0.f) * vm,
            fmaxf(__half2float(h[2]) * s + t, 0.f) * vm,
            fmaxf(__half2float(h[3]) * s + t, 0.f) * vm);
        *(float4*)(op + 4) = make_float4(
            fmaxf(__half2float(h[4]) * s + t, 0.f) * vm,
            fmaxf(__half2float(h[5]) * s + t, 0.f) * vm,
            fmaxf(__half2float(h[6]) * s + t, 0.f) * vm,
            fmaxf(__half2float(h[7]) * s + t, 0.f) * vm);
    }
}

// ---------------- launch ----------------
extern "C" void kernel_launch(void* const* d_in, const int* in_sizes, int n_in,
                              void* d_out, int out_size)
{
    const float* pc   = (const float*)d_in[0];
    const float* feat = (const float*)d_in[1];
    const float* img1 = (const float*)d_in[2];
    const float* img2 = (const float*)d_in[3];
    const int*   qv1  = (const int*)d_in[5];
    const float* npc  = (const float*)d_in[6];
    const float* w1 = (const float*)d_in[7];
    const float* g1 = (const float*)d_in[8];
    const float* b1 = (const float*)d_in[9];
    const float* w2 = (const float*)d_in[10];
    const float* g2 = (const float*)d_in[11];
    const float* b2 = (const float*)d_in[12];
    const float* w3 = (const float*)d_in[13];
    const float* g3 = (const float*)d_in[14];
    const float* b3 = (const float*)d_in[15];
    const float* w4 = (const float*)d_in[16];
    const float* g4 = (const float*)d_in[17];
    const float* b4 = (const float*)d_in[18];
    float* out = (float*)d_out;

    __half *pX0, *pY1, *pY2, *pY3, *pY4;
    __half *pW1, *pW2, *pW3, *pW4, *pScH, *pShH;
    float *pSum, *pSq, *pSc, *pSh, *pImgT;
    unsigned *pCnt;
    cudaGetSymbolAddress((void**)&pX0, g_X0h);
    cudaGetSymbolAddress((void**)&pY1, g_Y1h);
    cudaGetSymbolAddress((void**)&pY2, g_Y2h);
    cudaGetSymbolAddress((void**)&pY3, g_Y3h);
    cudaGetSymbolAddress((void**)&pY4, g_Y4h);
    cudaGetSymbolAddress((void**)&pW1, g_Wp1h);
    cudaGetSymbolAddress((void**)&pW2, g_Wp2h);
    cudaGetSymbolAddress((void**)&pW3, g_Wp3h);
    cudaGetSymbolAddress((void**)&pW4, g_Wp4h);
    cudaGetSymbolAddress((void**)&pSum, g_sum);
    cudaGetSymbolAddress((void**)&pSq,  g_sq);
    cudaGetSymbolAddress((void**)&pSc,  g_sc);
    cudaGetSymbolAddress((void**)&pSh,  g_sh);
    cudaGetSymbolAddress((void**)&pScH, g_scH);
    cudaGetSymbolAddress((void**)&pShH, g_shH);
    cudaGetSymbolAddress((void**)&pCnt, g_cnt);
    cudaGetSymbolAddress((void**)&pImgT, g_imgT);

    auto smemSz = [](int BM, int CIN) {
        int gemm = (BM * (CIN + 8) + 3 * 32 * (128 + 8) + 2 * CIN) * 2;
        int wrt  = (192 * 33 + 40) * 4;   // rgb writer stage
        return gemm > wrt ? gemm : wrt;
    };
    const int sm1 = smemSz(64, 96);
    const int sm2 = smemSz(128, 64);
    const int sm3 = smemSz(128, 128);

    static bool attr_done = false;
    if (!attr_done) {
        cudaFuncSetAttribute(k_gemm_h<64, 64, 96, 4, 256, false, 2>,
                             cudaFuncAttributeMaxDynamicSharedMemorySize, sm1);
        cudaFuncSetAttribute(k_gemm_h<128, 128, 64, 4, 256, true, 1>,
                             cudaFuncAttributeMaxDynamicSharedMemorySize, sm2);
        cudaFuncSetAttribute(k_gemm_h<128, 128, 128, 4, 256, true, 1>,
                             cudaFuncAttributeMaxDynamicSharedMemorySize, sm3);
        cudaFuncSetAttribute(k_gemm_h<128, 256, 128, 4, 256, true, 0>,
                             cudaFuncAttributeMaxDynamicSharedMemorySize, sm3);
        attr_done = true;
    }

    k_idx<<<B_, 256>>>(pc, npc, qv1);
    k_prep<<<32, 256>>>(w1, w2, w3, w4);
    k_timg<<<dim3(HW / 32, 192 / 32, B_), dim3(32, 32)>>>(img1, img2);
    k_gather<<<B_ * PCTR, 256>>>(pc, feat, npc);

    const int GXG = MTOT / (128 * 4);   // 256 gemm blocks, 4 tiles each
    const int WB1 = 512;                // rgb writer blocks
    const int WB  = 256;                // norm-out writer blocks

    // G1: 64 <- 96(pad of 67); writers: rgb1/rgb2 -> out ch [64,128) & [256,384)
    k_gemm_h<64, 64, 96, 4, 256, false, 2><<<dim3(GXG + WB1, 1), 256, sm1>>>(
        pW1, pX0, pY1, nullptr, nullptr,
        pSum + 0, pSq + 0, g1, b1, pSc + 0, pSh + 0, pScH + 0, pShH + 0, pCnt + 0,
        out, nullptr, nullptr, nullptr, pImgT, GXG, GXG, 0, 0);
    // G2: 128 <- 64, fragment-norm(L1); writers: out ch [0,64) from Y1
    k_gemm_h<128, 128, 64, 4, 256, true, 1><<<dim3(GXG + WB, 1), 256, sm2>>>(
        pW2, pY1, pY2, pScH + 0, pShH + 0,
        pSum + 256, pSq + 256, g2, b2, pSc + 256, pSh + 256, pScH + 256, pShH + 256, pCnt + 1,
        out, pY1, pSc + 0, pSh + 0, nullptr, GXG, GXG, 64, 0);
    // G3: 128 <- 128, fragment-norm(L2); writers: out ch [128,256) from Y2
    k_gemm_h<128, 128, 128, 4, 256, true, 1><<<dim3(GXG + WB, 1), 256, sm3>>>(
        pW3, pY2, pY3, pScH + 256, pShH + 256,
        pSum + 512, pSq + 512, g3, b3, pSc + 512, pSh + 512, pScH + 512, pShH + 512, pCnt + 2,
        out, pY2, pSc + 256, pSh + 256, nullptr, GXG, GXG, 128, 128);
    // G4: 256 <- 128, fragment-norm(L3), grid.y = 2, no writers
    k_gemm_h<128, 256, 128, 4, 256, true, 0><<<dim3(GXG, 2), 256, sm3>>>(
        pW4, pY3, pY4, pScH + 512, pShH + 512,
        pSum + 768, pSq + 768, g4, b4, pSc + 768, pSh + 768, pScH + 768, pShH + 768, pCnt + 3,
        out, nullptr, nullptr, nullptr, nullptr, GXG, GXG * 2, 0, 0);
    // out ch [384,640) from Y4
    k_out<<<2048, 256>>>(pY4, 3, 256, 384, out);
}

// round 13
// speedup vs baseline: 1.2775x; 1.0077x over previous
#include <cuda_runtime.h>
#include <cuda_fp16.h>
#include <math.h>

#define B_    16
#define NPTS  2048
#define PCTR  256
#define KNB   32
#define HW    1920
#define INFEA 64
#define MTOT  131072
#define EPSBN 1e-5f
#define DIST_ 0.5f
#define OUTSTRIDE 5242880   // 640*8192

// ---------------- scratch ----------------
__device__ __half g_X0h[96 * MTOT];   // channels 67..95 stay zero
__device__ __half g_Y1h[64 * MTOT];
__device__ __half g_Y2h[128 * MTOT];
__device__ __half g_Y3h[128 * MTOT];
__device__ __half g_Y4h[256 * MTOT];
__device__ float  g_imgT[B_ * HW * 192];    // pixel-major fused img1+img2
__device__ __half g_featT[B_ * NPTS * 64];  // pixel-major feat (half)
__device__ int    g_idx[MTOT];
__device__ int    g_ridx[MTOT];
__device__ float  g_vmask[B_ * PCTR];
__device__ __half g_Wp1h[64 * 96];
__device__ __half g_Wp2h[128 * 64];
__device__ __half g_Wp3h[128 * 128];
__device__ __half g_Wp4h[256 * 128];
__device__ float  g_sum[4][256];
__device__ float  g_sq[4][256];
__device__ float  g_sc[4][256];
__device__ float  g_sh[4][256];
__device__ __half g_scH[4][256];
__device__ __half g_shH[4][256];
__device__ unsigned g_cnt[4];

__device__ __forceinline__ void cp16(void* dst_smem, const void* src) {
    unsigned d = (unsigned)__cvta_generic_to_shared(dst_smem);
    asm volatile("cp.async.cg.shared.global [%0], [%1], 16;" :: "r"(d), "l"(src));
}
__device__ __forceinline__ void ldsm_x4(unsigned* r, unsigned a) {
    asm volatile("ldmatrix.sync.aligned.m8n8.x4.shared.b16 {%0,%1,%2,%3}, [%4];"
        : "=r"(r[0]), "=r"(r[1]), "=r"(r[2]), "=r"(r[3]) : "r"(a));
}
__device__ __forceinline__ void ldsm_x4_t(unsigned* r, unsigned a) {
    asm volatile("ldmatrix.sync.aligned.m8n8.x4.trans.shared.b16 {%0,%1,%2,%3}, [%4];"
        : "=r"(r[0]), "=r"(r[1]), "=r"(r[2]), "=r"(r[3]) : "r"(a));
}
__device__ __forceinline__ unsigned nrm2(unsigned v, unsigned s, unsigned t) {
    __half2 r = __hfma2(*(__half2*)&v, *(__half2*)&s, *(__half2*)&t);
    r = __hmax2(r, __half2(__half(0.f), __half(0.f)));
    return *(unsigned*)&r;
}

// ---------------- depth-ball query (+ zero stats & counters) ----------------
__global__ void k_idx(const float* __restrict__ pc,
                      const float* __restrict__ npc,
                      const int*   __restrict__ qv1)
{
    __shared__ float zs[NPTS];
    __shared__ int   stage[8][32];
    const int b   = blockIdx.x;
    const int tid = threadIdx.x;

    if (b == 0) {
        float* ps = &g_sum[0][0];
        float* pq = &g_sq[0][0];
        for (int i = tid; i < 4 * 256; i += 256) { ps[i] = 0.f; pq[i] = 0.f; }
        if (tid < 4) g_cnt[tid] = 0u;
    }
    for (int i = tid; i < NPTS; i += 256) zs[i] = pc[(b * 3 + 2) * NPTS + i];
    __syncthreads();

    const int w = tid >> 5, lane = tid & 31;
    for (int jj = 0; jj < 32; jj++) {
        const int j = w * 32 + jj;
        const float cz = npc[(b * 3 + 2) * PCTR + j];
        int cnt = 0;
        for (int c = 0; c < NPTS / 32; c++) {
            const int n = c * 32 + lane;
            const bool hit = fabsf(zs[n] - cz) < DIST_;
            const unsigned bal = __ballot_sync(0xffffffffu, hit);
            if (hit) {
                const int pos = cnt + __popc(bal & ((1u << lane) - 1u));
                if (pos < 32) stage[w][pos] = n;
            }
            cnt += __popc(bal);
            if (cnt >= 32) break;
        }
        __syncwarp();
        const int cc = min(cnt, 32);
        const int first = (cnt > 0) ? stage[w][0] : 0;
        const int v = (lane < cc) ? stage[w][lane] : first;
        const int gbase = (b * PCTR + j) * KNB;
        g_idx[gbase + lane]  = v;
        g_ridx[gbase + lane] = qv1[b * NPTS + v];
        if (lane == 0) g_vmask[b * PCTR + j] = (cnt > 0) ? 1.f : 0.f;
        __syncwarp();
    }
}

// ---------------- weight packing ----------------
__device__ __forceinline__ void packW(const float* w, __half* dst,
                                      int M, int CIN, int CINP, int tid, int nthr)
{
    const int tot = M * CINP;
    for (int i = tid; i < tot; i += nthr) {
        const int m = i / CINP, k = i - m * CINP;
        dst[i] = __float2half((k < CIN) ? w[m * CIN + k] : 0.f);
    }
}

__global__ void k_prep(const float* __restrict__ w1, const float* __restrict__ w2,
                       const float* __restrict__ w3, const float* __restrict__ w4)
{
    const int tid = blockIdx.x * blockDim.x + threadIdx.x;
    const int nthr = gridDim.x * blockDim.x;
    packW(w1, g_Wp1h, 64, 67, 96, tid, nthr);
    packW(w2, g_Wp2h, 128, 64, 64, tid, nthr);
    packW(w3, g_Wp3h, 128, 128, 128, tid, nthr);
    packW(w4, g_Wp4h, 256, 128, 128, tid, nthr);
}

// ---------------- transposes: imgs -> [B][HW][192] fp32, feat -> [B][N][64] half ----------------
__global__ void k_timg(const float* __restrict__ img1, const float* __restrict__ img2,
                       const float* __restrict__ feat)
{
    __shared__ float tile[32][33];
    const int b  = blockIdx.z;
    const int p0 = blockIdx.x * 32;
    const int yb = blockIdx.y;
    const int tx = threadIdx.x, ty = threadIdx.y;

    if (yb < 6) {           // img transpose
        if (p0 >= HW) return;
        const int c0 = yb * 32;
        const int c = c0 + ty;
        const float* src = (c < 64) ? &img1[(size_t)(b * 64 + c) * HW]
                                    : &img2[(size_t)(b * 128 + (c - 64)) * HW];
        tile[ty][tx] = src[p0 + tx];
        __syncthreads();
        g_imgT[((size_t)b * HW + p0 + ty) * 192 + c0 + tx] = tile[tx][ty];
    } else {                // feat transpose (p0 in [0,2048))
        const int c0 = (yb - 6) * 32;
        tile[ty][tx] = feat[(size_t)(b * 64 + c0 + ty) * NPTS + p0 + tx];
        __syncthreads();
        g_featT[((size_t)b * NPTS + p0 + ty) * 64 + c0 + tx] =
            __float2half(tile[tx][ty]);
    }
}

// ---------------- gather X0 (half): coalesced rows from featT ----------------
__global__ void k_gather(const float* __restrict__ pc,
                         const float* __restrict__ npc)
{
    __shared__ __align__(16) __half sm[64 * 32];
    __shared__ int    s_idx[32];
    __shared__ float  s_np[3];
    const int g = blockIdx.x;
    const int b = g >> 8;
    const int j = g & 255;
    const int t = threadIdx.x;
    const int mbase = g * KNB;

    if (t < 32) s_idx[t] = g_idx[mbase + t];
    if (t >= 32 && t < 35) s_np[t - 32] = npc[(b * 3 + (t - 32)) * PCTR + j];
    __syncthreads();

    // pc channels (3 x 32) — tiny scattered reads
    if (t < 96) {
        const int c = t >> 5, k = t & 31;
        g_X0h[c * MTOT + mbase + k] =
            __float2half(pc[(b * 3 + c) * NPTS + s_idx[k]] - s_np[c]);
    }

    // feat: 32 rows x 64 half, one uint4 per thread (256 = 32*8)
    {
        const int k = t >> 3, q = t & 7;
        const uint4 v = *(const uint4*)&g_featT[((size_t)b * NPTS + s_idx[k]) * 64 + q * 8];
        const __half* hv = (const __half*)&v;
#pragma unroll
        for (int jj = 0; jj < 8; jj++) sm[(q * 8 + jj) * 32 + k] = hv[jj];
    }
    __syncthreads();

    // write X0 channel-major: 64 ch x 4 uint4 = 256 items
    {
        const int c = t >> 2, q = t & 3;
        *(uint4*)&g_X0h[(3 + c) * MTOT + mbase + q * 8] = *(uint4*)&sm[c * 32 + q * 8];
    }
}

// ---------------- multi-tile fp16 TC GEMM + embedded writer blocks ----------------
// WMODE 0: pure GEMM. WMODE 1: writers emit out = relu(wsc*wY+wsh)*vm.
// WMODE 2: writers emit rgb1/rgb2 from pixel-major imgT (coalesced).
template <int BM, int CTOT, int CIN, int TILES, int THREADS, bool NORM_IN, int WMODE>
__global__ void __launch_bounds__(THREADS)
k_gemm_h(const __half* __restrict__ Wp, const __half* __restrict__ X,
         __half* __restrict__ Y,
         const __half* __restrict__ iscH, const __half* __restrict__ ishH,
         float* __restrict__ osum, float* __restrict__ osq,
         const float* __restrict__ gam, const float* __restrict__ bet,
         float* __restrict__ sc, float* __restrict__ sh,
         __half* __restrict__ scH, __half* __restrict__ shH,
         unsigned* __restrict__ cnt,
         float* __restrict__ out,
         const __half* __restrict__ wY,
         const float* __restrict__ wsc, const float* __restrict__ wsh,
         const float* __restrict__ imgT,
         int GXG, int ngemm, int wC, int wcbase)
{
    constexpr int BN = 128, BK = 32, PIPE = 3;
    constexpr int NITER = CIN / BK;
    constexpr int TOT = TILES * NITER;
    constexpr int WROW = CIN + 8;
    constexpr int BROW = BN + 8;
    constexpr int WARPS_M = THREADS / 128;
    constexpr int WTM = BM / WARPS_M;
    constexpr int MI = WTM / 16;
    constexpr int WCH = CIN / 8;

    const int tid = threadIdx.x;
    extern __shared__ __align__(16) __half dsm[];

    // ---------- embedded writer blocks ----------
    if (WMODE != 0 && (int)blockIdx.x >= GXG) {
        const int wb  = blockIdx.x - GXG;
        const int WBn = gridDim.x - GXG;
        if (WMODE == 1) {
            const int T = wC * (MTOT / 8);
            for (int e = wb * THREADS + tid; e < T; e += WBn * THREADS) {
                const int c = e / (MTOT / 8);
                const int m = (e - c * (MTOT / 8)) * 8;
                const uint4 r = *(const uint4*)&wY[(size_t)c * MTOT + m];
                const __half* h = (const __half*)&r;
                const float s = wsc[c], t = wsh[c];
                const float vm = g_vmask[m >> 5];
                const int bb = m >> 13, rem = m & 8191;
                float* op = &out[(long)bb * OUTSTRIDE + (long)(wcbase + c) * 8192 + rem];
                *(float4*)op = make_float4(
                    fmaxf(__half2float(h[0]) * s + t, 0.f) * vm,
                    fmaxf(__half2float(h[1]) * s + t, 0.f) * vm,
                    fmaxf(__half2float(h[2]) * s + t, 0.f) * vm,
                    fmaxf(__half2float(h[3]) * s + t, 0.f) * vm);
                *(float4*)(op + 4) = make_float4(
                    fmaxf(__half2float(h[4]) * s + t, 0.f) * vm,
                    fmaxf(__half2float(h[5]) * s + t, 0.f) * vm,
                    fmaxf(__half2float(h[6]) * s + t, 0.f) * vm,
                    fmaxf(__half2float(h[7]) * s + t, 0.f) * vm);
            }
        } else {
            // rgb writer: coalesced rows from imgT, smem-staged transpose to out
            float* sm = (float*)dsm;                 // [192][33] stage
            int*   rp = (int*)(sm + 192 * 33);       // 32 pixel ids
            float* vmp = sm + 192 * 33 + 32;
            for (int g0 = wb; g0 < B_ * PCTR; g0 += WBn) {
                const int b = g0 >> 8, j = g0 & 255;
                if (tid < 32) rp[tid] = g_ridx[g0 * KNB + tid];
                if (tid == 32) vmp[0] = g_vmask[g0];
                __syncthreads();
                const float vm = vmp[0];
                for (int e = tid; e < 32 * 48; e += THREADS) {
                    const int k = e / 48, c4 = e - k * 48;
                    const float4 v =
                        ((const float4*)&imgT[((size_t)b * HW + rp[k]) * 192])[c4];
                    sm[(c4 * 4 + 0) * 33 + k] = v.x;
                    sm[(c4 * 4 + 1) * 33 + k] = v.y;
                    sm[(c4 * 4 + 2) * 33 + k] = v.z;
                    sm[(c4 * 4 + 3) * 33 + k] = v.w;
                }
                __syncthreads();
                const long ob = (long)b * OUTSTRIDE + (long)j * 32;
                for (int e = tid; e < 192 * 8; e += THREADS) {
                    const int c = e >> 3, q = e & 7;
                    const int oc = (c < 64) ? 64 + c : 192 + c;   // 256+(c-64)
                    const float* sp = &sm[c * 33 + q * 4];
                    float4 o = make_float4(sp[0] * vm, sp[1] * vm, sp[2] * vm, sp[3] * vm);
                    *(float4*)&out[ob + (long)oc * 8192 + q * 4] = o;
                }
                __syncthreads();
            }
        }
        return;
    }

    // ---------- GEMM blocks ----------
    __half* Ws = dsm;                               // BM * WROW
    __half* Bs = Ws + BM * WROW;                    // PIPE * BK * BROW
    __half* sS = Bs + PIPE * BK * BROW;             // CIN
    __half* sT = sS + CIN;                          // CIN
    __shared__ int s_last;

    const int lane = tid & 31;
    const int warp = tid >> 5;
    const int wm0  = (warp >> 2) * WTM;
    const int wn0  = (warp & 3) * 32;
    const int bn0  = blockIdx.x * (BN * TILES);
    const int bm0  = blockIdx.y * BM;
    const int grp  = lane >> 2;
    const int tig  = lane & 3;

    const unsigned ws_u = (unsigned)__cvta_generic_to_shared(Ws);
    const unsigned bs_u = (unsigned)__cvta_generic_to_shared(Bs);

    for (int f = tid; f < BM * WCH; f += THREADS) {
        const int m = f / WCH, ch = f % WCH;
        cp16(&Ws[m * WROW + ch * 8], &Wp[(size_t)(bm0 + m) * CIN + ch * 8]);
    }
    if (NORM_IN) {
        for (int e = tid; e < CIN; e += THREADS) { sS[e] = iscH[e]; sT[e] = ishH[e]; }
    }
    asm volatile("cp.async.commit_group;");

    auto cpB = [&](int g) {
        const int stg = g % PIPE;
        const int tile = g / NITER, it = g - tile * NITER;
        const int nb = bn0 + tile * BN;
        for (int e = tid; e < BK * (BN / 8); e += THREADS) {
            const int kk = e >> 4, ch = e & 15;
            cp16(&Bs[(stg * BK + kk) * BROW + ch * 8],
                 &X[(size_t)(it * BK + kk) * MTOT + nb + ch * 8]);
        }
    };
#pragma unroll
    for (int s = 0; s < PIPE - 1; s++) {
        if (s < TOT) cpB(s);
        asm volatile("cp.async.commit_group;");
    }
    asm volatile("cp.async.wait_group %0;" :: "n"(PIPE - 2));
    __syncthreads();

    float acc[MI][4][4];
#pragma unroll
    for (int mi = 0; mi < MI; mi++)
#pragma unroll
        for (int ni = 0; ni < 4; ni++)
#pragma unroll
            for (int r = 0; r < 4; r++) acc[mi][ni][r] = 0.f;

    float sSr[MI][2], sQr[MI][2];
#pragma unroll
    for (int mi = 0; mi < MI; mi++) {
        sSr[mi][0] = sSr[mi][1] = 0.f;
        sQr[mi][0] = sQr[mi][1] = 0.f;
    }

    const int a_row = (lane & 7) + ((lane >> 3) & 1) * 8;
    const int a_kq  = ((lane >> 4) & 1) * 8;
    const int b_kr  = ((lane >> 3) & 1) * 8 + (lane & 7);
    const int b_nq  = ((lane >> 4) & 1) * 8;

    for (int g = 0; g < TOT; g++) {
        const int stg = g % PIPE;
        const int tile = g / NITER, it = g - tile * NITER;
        if (g + PIPE - 1 < TOT) cpB(g + PIPE - 1);
        asm volatile("cp.async.commit_group;");

#pragma unroll
        for (int kk = 0; kk < 2; kk++) {
            const int kbase = it * BK + kk * 16;
            unsigned a[MI][4], bfr[4][2];
#pragma unroll
            for (int mi = 0; mi < MI; mi++) {
                const unsigned addr = ws_u +
                    (((wm0 + mi * 16 + a_row) * WROW) + kbase + a_kq) * 2;
                ldsm_x4(a[mi], addr);
            }
#pragma unroll
            for (int ni2 = 0; ni2 < 2; ni2++) {
                unsigned t4[4];
                const unsigned addr = bs_u + ((stg * BK + kk * 16 + b_kr) * BROW +
                                              wn0 + ni2 * 16 + b_nq) * 2;
                ldsm_x4_t(t4, addr);
                bfr[ni2 * 2][0] = t4[0]; bfr[ni2 * 2][1] = t4[1];
                bfr[ni2 * 2 + 1][0] = t4[2]; bfr[ni2 * 2 + 1][1] = t4[3];
            }
            if (NORM_IN) {
                const int k0 = kbase + 2 * tig;
                const unsigned s0 = *(const unsigned*)&sS[k0];
                const unsigned t0 = *(const unsigned*)&sT[k0];
                const unsigned s1 = *(const unsigned*)&sS[k0 + 8];
                const unsigned t1 = *(const unsigned*)&sT[k0 + 8];
#pragma unroll
                for (int ni = 0; ni < 4; ni++) {
                    bfr[ni][0] = nrm2(bfr[ni][0], s0, t0);
                    bfr[ni][1] = nrm2(bfr[ni][1], s1, t1);
                }
            }
#pragma unroll
            for (int mi = 0; mi < MI; mi++)
#pragma unroll
                for (int ni = 0; ni < 4; ni++) {
                    asm volatile(
                        "mma.sync.aligned.m16n8k16.row.col.f32.f16.f16.f32 "
                        "{%0,%1,%2,%3}, {%4,%5,%6,%7}, {%8,%9}, {%0,%1,%2,%3};"
                        : "+f"(acc[mi][ni][0]), "+f"(acc[mi][ni][1]),
                          "+f"(acc[mi][ni][2]), "+f"(acc[mi][ni][3])
                        : "r"(a[mi][0]), "r"(a[mi][1]), "r"(a[mi][2]), "r"(a[mi][3]),
                          "r"(bfr[ni][0]), "r"(bfr[ni][1]));
                }
        }

        if (it == NITER - 1) {
            const int nb = bn0 + tile * BN;
#pragma unroll
            for (int mi = 0; mi < MI; mi++) {
                const int r1 = wm0 + mi * 16 + grp;
                const int r2 = r1 + 8;
#pragma unroll
                for (int ni = 0; ni < 4; ni++) {
                    const int col = nb + wn0 + ni * 8 + tig * 2;
                    const float c0 = acc[mi][ni][0], c1 = acc[mi][ni][1];
                    const float c2 = acc[mi][ni][2], c3 = acc[mi][ni][3];
                    *(__half2*)&Y[(size_t)(bm0 + r1) * MTOT + col] = __floats2half2_rn(c0, c1);
                    *(__half2*)&Y[(size_t)(bm0 + r2) * MTOT + col] = __floats2half2_rn(c2, c3);
                    sSr[mi][0] += c0 + c1;  sQr[mi][0] += c0 * c0 + c1 * c1;
                    sSr[mi][1] += c2 + c3;  sQr[mi][1] += c2 * c2 + c3 * c3;
                    acc[mi][ni][0] = 0.f; acc[mi][ni][1] = 0.f;
                    acc[mi][ni][2] = 0.f; acc[mi][ni][3] = 0.f;
                }
            }
        }
        asm volatile("cp.async.wait_group %0;" :: "n"(PIPE - 2));
        __syncthreads();
    }

    // ---- epilogue: block stats reduction (aliases B smem) ----
    float* redS = (float*)Bs;
    float* redQ = redS + BM;
    for (int e = tid; e < BM; e += THREADS) { redS[e] = 0.f; redQ[e] = 0.f; }
    __syncthreads();
#pragma unroll
    for (int mi = 0; mi < MI; mi++) {
        const int r1 = wm0 + mi * 16 + grp;
        atomicAdd(&redS[r1], sSr[mi][0]);
        atomicAdd(&redQ[r1], sQr[mi][0]);
        atomicAdd(&redS[r1 + 8], sSr[mi][1]);
        atomicAdd(&redQ[r1 + 8], sQr[mi][1]);
    }
    __syncthreads();
    for (int e = tid; e < BM; e += THREADS) {
        atomicAdd(&osum[bm0 + e], redS[e]);
        atomicAdd(&osq[bm0 + e], redQ[e]);
    }

    // ---- last GEMM block finalizes BN scale/shift ----
    __threadfence();
    __syncthreads();
    if (tid == 0) {
        const unsigned done = atomicAdd(cnt, 1u);
        s_last = (done == (unsigned)(ngemm - 1)) ? 1 : 0;
    }
    __syncthreads();
    if (s_last) {
        __threadfence();
        for (int c = tid; c < CTOT; c += THREADS) {
            const float m = osum[c] * (1.f / (float)MTOT);
            const float v = osq[c] * (1.f / (float)MTOT) - m * m;
            const float s = gam[c] * rsqrtf(v + EPSBN);
            const float t = bet[c] - m * s;
            sc[c] = s;
            sh[c] = t;
            scH[c] = __float2half(s);
            shH[c] = __float2half(t);
        }
    }
}

// ---------------- out writer: out[cbase..cbase+C) = relu(s*Y+t)*vm (fp32) ----------------
__global__ void k_out(const __half* __restrict__ Y, int layer, int C, int cbase,
                      float* __restrict__ out)
{
    const int T = C * (MTOT / 8);
    for (int e = blockIdx.x * blockDim.x + threadIdx.x; e < T;
         e += gridDim.x * blockDim.x) {
        const int c = e / (MTOT / 8);
        const int m = (e - c * (MTOT / 8)) * 8;
        const uint4 r = *(const uint4*)&Y[(size_t)c * MTOT + m];
        const __half* h = (const __half*)&r;
        const float s = g_sc[layer][c], t = g_sh[layer][c];
        const float vm = g_vmask[m >> 5];
        const int bb = m >> 13, rem = m & 8191;
        float* op = &out[(long)bb * OUTSTRIDE + (long)(cbase + c) * 8192 + rem];
        *(float4*)op = make_float4(
            fmaxf(__half2float(h[0]) * s + t, 0.f) * vm,
            fmaxf(__half2float(h[1]) * s + t, 0.f) * vm,
            fmaxf(__half2float(h[2]) * s + t, 0.f) * vm,
            fmaxf(__half2float(h[3]) * s + t, 0.f) * vm);
        *(float4*)(op + 4) = make_float4(
            fmaxf(__half2float(h[4]) * s + t, 0.f) * vm,
            fmaxf(__half2float(h[5]) * s + t, 0.f) * vm,
            fmaxf(__half2float(h[6]) * s + t, 0.f) * vm,
            fmaxf(__half2float(h[7]) * s + t, 0.f) * vm);
    }
}

// ---------------- launch ----------------
extern "C" void kernel_launch(void* const* d_in, const int* in_sizes, int n_in,
                              void* d_out, int out_size)
{
    const float* pc   = (const float*)d_in[0];
    const float* feat = (const float*)d_in[1];
    const float* img1 = (const float*)d_in[2];
    const float* img2 = (const float*)d_in[3];
    const int*   qv1  = (const int*)d_in[5];
    const float* npc  = (const float*)d_in[6];
    const float* w1 = (const float*)d_in[7];
    const float* g1 = (const float*)d_in[8];
    const float* b1 = (const float*)d_in[9];
    const float* w2 = (const float*)d_in[10];
    const float* g2 = (const float*)d_in[11];
    const float* b2 = (const float*)d_in[12];
    const float* w3 = (const float*)d_in[13];
    const float* g3 = (const float*)d_in[14];
    const float* b3 = (const float*)d_in[15];
    const float* w4 = (const float*)d_in[16];
    const float* g4 = (const float*)d_in[17];
    const float* b4 = (const float*)d_in[18];
    float* out = (float*)d_out;

    __half *pX0, *pY1, *pY2, *pY3, *pY4;
    __half *pW1, *pW2, *pW3, *pW4, *pScH, *pShH;
    float *pSum, *pSq, *pSc, *pSh, *pImgT;
    unsigned *pCnt;
    cudaGetSymbolAddress((void**)&pX0, g_X0h);
    cudaGetSymbolAddress((void**)&pY1, g_Y1h);
    cudaGetSymbolAddress((void**)&pY2, g_Y2h);
    cudaGetSymbolAddress((void**)&pY3, g_Y3h);
    cudaGetSymbolAddress((void**)&pY4, g_Y4h);
    cudaGetSymbolAddress((void**)&pW1, g_Wp1h);
    cudaGetSymbolAddress((void**)&pW2, g_Wp2h);
    cudaGetSymbolAddress((void**)&pW3, g_Wp3h);
    cudaGetSymbolAddress((void**)&pW4, g_Wp4h);
    cudaGetSymbolAddress((void**)&pSum, g_sum);
    cudaGetSymbolAddress((void**)&pSq,  g_sq);
    cudaGetSymbolAddress((void**)&pSc,  g_sc);
    cudaGetSymbolAddress((void**)&pSh,  g_sh);
    cudaGetSymbolAddress((void**)&pScH, g_scH);
    cudaGetSymbolAddress((void**)&pShH, g_shH);
    cudaGetSymbolAddress((void**)&pCnt, g_cnt);
    cudaGetSymbolAddress((void**)&pImgT, g_imgT);

    auto smemSz = [](int BM, int CIN) {
        int gemm = (BM * (CIN + 8) + 3 * 32 * (128 + 8) + 2 * CIN) * 2;
        int wrt  = (192 * 33 + 40) * 4;   // rgb writer stage
        return gemm > wrt ? gemm : wrt;
    };
    const int sm1 = smemSz(64, 96);
    const int sm2 = smemSz(128, 64);
    const int sm3 = smemSz(128, 128);

    static bool attr_done = false;
    if (!attr_done) {
        cudaFuncSetAttribute(k_gemm_h<64, 64, 96, 4, 256, false, 2>,
                             cudaFuncAttributeMaxDynamicSharedMemorySize, sm1);
        cudaFuncSetAttribute(k_gemm_h<128, 128, 64, 4, 256, true, 1>,
                             cudaFuncAttributeMaxDynamicSharedMemorySize, sm2);
        cudaFuncSetAttribute(k_gemm_h<128, 128, 128, 4, 256, true, 1>,
                             cudaFuncAttributeMaxDynamicSharedMemorySize, sm3);
        cudaFuncSetAttribute(k_gemm_h<128, 256, 128, 4, 256, true, 0>,
                             cudaFuncAttributeMaxDynamicSharedMemorySize, sm3);
        attr_done = true;
    }

    k_idx<<<B_, 256>>>(pc, npc, qv1);
    k_prep<<<32, 256>>>(w1, w2, w3, w4);
    // img transpose (y=0..5) + feat transpose (y=6..7); x covers max(60,64)=64
    k_timg<<<dim3(64, 8, B_), dim3(32, 32)>>>(img1, img2, feat);
    k_gather<<<B_ * PCTR, 256>>>(pc, npc);

    const int GXG = MTOT / (128 * 4);   // 256 gemm blocks, 4 tiles each
    const int WB1 = 512;                // rgb writer blocks
    const int WB  = 256;                // norm-out writer blocks

    // G1: 64 <- 96(pad of 67); writers: rgb1/rgb2 -> out ch [64,128) & [256,384)
    k_gemm_h<64, 64, 96, 4, 256, false, 2><<<dim3(GXG + WB1, 1), 256, sm1>>>(
        pW1, pX0, pY1, nullptr, nullptr,
        pSum + 0, pSq + 0, g1, b1, pSc + 0, pSh + 0, pScH + 0, pShH + 0, pCnt + 0,
        out, nullptr, nullptr, nullptr, pImgT, GXG, GXG, 0, 0);
    // G2: 128 <- 64, fragment-norm(L1); writers: out ch [0,64) from Y1
    k_gemm_h<128, 128, 64, 4, 256, true, 1><<<dim3(GXG + WB, 1), 256, sm2>>>(
        pW2, pY1, pY2, pScH + 0, pShH + 0,
        pSum + 256, pSq + 256, g2, b2, pSc + 256, pSh + 256, pScH + 256, pShH + 256, pCnt + 1,
        out, pY1, pSc + 0, pSh + 0, nullptr, GXG, GXG, 64, 0);
    // G3: 128 <- 128, fragment-norm(L2); writers: out ch [128,256) from Y2
    k_gemm_h<128, 128, 128, 4, 256, true, 1><<<dim3(GXG + WB, 1), 256, sm3>>>(
        pW3, pY2, pY3, pScH + 256, pShH + 256,
        pSum + 512, pSq + 512, g3, b3, pSc + 512, pSh + 512, pScH + 512, pShH + 512, pCnt + 2,
        out, pY2, pSc + 256, pSh + 256, nullptr, GXG, GXG, 128, 128);
    // G4: 256 <- 128, fragment-norm(L3), grid.y = 2, no writers
    k_gemm_h<128, 256, 128, 4, 256, true, 0><<<dim3(GXG, 2), 256, sm3>>>(
        pW4, pY3, pY4, pScH + 512, pShH + 512,
        pSum + 768, pSq + 768, g4, b4, pSc + 768, pSh + 768, pScH + 768, pShH + 768, pCnt + 3,
        out, nullptr, nullptr, nullptr, nullptr, GXG, GXG * 2, 0, 0);
    // out ch [384,640) from Y4
    k_out<<<2048, 256>>>(pY4, 3, 256, 384, out);
}